// round 11
// baseline (speedup 1.0000x reference)
#include <cuda_runtime.h>
#include <cuda_bf16.h>
#include <cstdint>

namespace {
constexpr int D=128, D2=256, NFEAT=9, VOC=100, KS=3, LAY=3, NPAD=100096;
constexpr int EMAX=600000;
constexpr int BM=128, BN=128, BK=32;
// pure-bf16 GEMM smem: Ah/Al 2 stages x 128x40, Bh/Bl 2 stages x 32x136 (bf16)
constexpr int OFF_AH=0, OFF_AL=20480, OFF_BH=40960, OFF_BL=58368;
constexpr int SMEM_BYTES=75776;
}

__device__ float g_h   [NPAD * D];
__device__ float g_y1  [KS * NPAD * D2];
__device__ float g_hacc[NPAD * D];
__device__ __align__(16) __nv_bfloat16 g_aggH[KS * NPAD * D];
__device__ __align__(16) __nv_bfloat16 g_aggL[KS * NPAD * D];
__device__ __align__(16) __nv_bfloat16 g_zcH [NPAD * D2];
__device__ __align__(16) __nv_bfloat16 g_zcL [NPAD * D2];
__device__ float g_sum  [KS * D2];
__device__ float g_sq   [KS * D2];
__device__ float g_scale[KS * D2];
__device__ float g_shift[KS * D2];
__device__ float g_scaleD[D];
__device__ float g_shiftD[D];
__device__ float g_aw   [KS];
__device__ __align__(16) __nv_bfloat16 g_W1h[LAY * D * D2];
__device__ __align__(16) __nv_bfloat16 g_W1l[LAY * D * D2];
__device__ __align__(16) __nv_bfloat16 g_W2h[LAY * D2 * D];
__device__ __align__(16) __nv_bfloat16 g_W2l[LAY * D2 * D];
// CSR scratch (built once per launch)
__device__ int g_deg   [KS * NPAD];
__device__ int g_dcur  [KS * NPAD];
__device__ int g_rowptr[KS * (NPAD + 1)];
__device__ int g_csrc  [KS * EMAX];

// ---------------- PTX helpers ----------------
__device__ __forceinline__ uint32_t smem_u32(const void* p){return (uint32_t)__cvta_generic_to_shared(p);}
__device__ __forceinline__ void ldsm_x4(uint32_t r[4], uint32_t a){
    asm volatile("ldmatrix.sync.aligned.m8n8.x4.shared.b16 {%0,%1,%2,%3},[%4];"
                 :"=r"(r[0]),"=r"(r[1]),"=r"(r[2]),"=r"(r[3]):"r"(a));
}
__device__ __forceinline__ void ldsm_x4t(uint32_t r[4], uint32_t a){
    asm volatile("ldmatrix.sync.aligned.m8n8.x4.trans.shared.b16 {%0,%1,%2,%3},[%4];"
                 :"=r"(r[0]),"=r"(r[1]),"=r"(r[2]),"=r"(r[3]):"r"(a));
}
__device__ __forceinline__ void mma16816(float c[4], const uint32_t a[4], const uint32_t* b){
    asm volatile("mma.sync.aligned.m16n8k16.row.col.f32.bf16.bf16.f32 "
                 "{%0,%1,%2,%3},{%4,%5,%6,%7},{%8,%9},{%0,%1,%2,%3};"
                 :"+f"(c[0]),"+f"(c[1]),"+f"(c[2]),"+f"(c[3])
                 :"r"(a[0]),"r"(a[1]),"r"(a[2]),"r"(a[3]),"r"(b[0]),"r"(b[1]));
}
__device__ __forceinline__ void cp16(void* d, const void* s){
    asm volatile("cp.async.cg.shared.global [%0],[%1],16;"::"r"(smem_u32(d)),"l"(s):"memory");
}
__device__ __forceinline__ uint32_t bf2(__nv_bfloat16 a, __nv_bfloat16 b){
    __nv_bfloat162 t; t.x=a; t.y=b; return *reinterpret_cast<uint32_t*>(&t);
}
__device__ __forceinline__ void split4(float4 v, uint2& hp, uint2& lp){
    __nv_bfloat16 h0=__float2bfloat16(v.x), h1=__float2bfloat16(v.y);
    __nv_bfloat16 h2=__float2bfloat16(v.z), h3=__float2bfloat16(v.w);
    hp = make_uint2(bf2(h0,h1), bf2(h2,h3));
    lp = make_uint2(
        bf2(__float2bfloat16(v.x-__bfloat162float(h0)), __float2bfloat16(v.y-__bfloat162float(h1))),
        bf2(__float2bfloat16(v.z-__bfloat162float(h2)), __float2bfloat16(v.w-__bfloat162float(h3))));
}

// ---------------- small kernels ----------------
__global__ void embed_kernel(const int* __restrict__ x, const float* __restrict__ emb,
                             float* __restrict__ H, int N)
{
    int gt = blockIdx.x*blockDim.x+threadIdx.x;
    int node = gt>>5, lane = gt&31;
    if (node >= N) return;
    float4 acc = make_float4(0.f,0.f,0.f,0.f);
#pragma unroll
    for (int f=0; f<NFEAT; f++){
        int idx = x[node*NFEAT+f];
        float4 v = ((const float4*)(emb + ((size_t)f*VOC+idx)*D))[lane];
        acc.x+=v.x; acc.y+=v.y; acc.z+=v.z; acc.w+=v.w;
    }
    ((float4*)(H+(size_t)node*D))[lane] = acc;
}

__global__ void softmax3_kernel(const float* __restrict__ alpha, float* __restrict__ a)
{
    float a0=alpha[0],a1=alpha[1],a2=alpha[2];
    float m=fmaxf(a0,fmaxf(a1,a2));
    float e0=expf(a0-m),e1=expf(a1-m),e2=expf(a2-m);
    float inv=1.f/(e0+e1+e2);
    a[0]=e0*inv; a[1]=e1*inv; a[2]=e2*inv;
}

__global__ void wsplit_kernel(const float* __restrict__ W1, const float* __restrict__ W2,
                              __nv_bfloat16* __restrict__ w1h, __nv_bfloat16* __restrict__ w1l,
                              __nv_bfloat16* __restrict__ w2h, __nv_bfloat16* __restrict__ w2l)
{
    int i = blockIdx.x*blockDim.x+threadIdx.x;
    const int tot = LAY*D*D2;
    if (i < tot){
        float v = W1[i];
        __nv_bfloat16 h = __float2bfloat16(v);
        w1h[i] = h;
        w1l[i] = __float2bfloat16(v-__bfloat162float(h));
    } else if (i < 2*tot){
        int j = i-tot;
        float v = W2[j];
        __nv_bfloat16 h = __float2bfloat16(v);
        w2h[j] = h;
        w2l[j] = __float2bfloat16(v-__bfloat162float(h));
    }
}

// ---------------- CSR build (once per launch) ----------------
__global__ void hist_kernel(const int* __restrict__ ke, int* __restrict__ deg, int E, int N)
{
    int i = blockIdx.x*blockDim.x+threadIdx.x;
    if (i >= KS*E) return;
    int k = i/E, e = i - k*E;
    int d = ke[(size_t)(k*2+1)*E + e];
    atomicAdd(&deg[k*N + d], 1);
}

__global__ void scan_kernel(const int* __restrict__ deg, int* __restrict__ rowptr,
                            int* __restrict__ dcur, int N, int E)
{
    const int T = 1024;
    int k = blockIdx.x, t = threadIdx.x;
    int chunk = (N + T - 1)/T;
    int lo = t*chunk, hi = min(lo+chunk, N);
    int s = 0;
    for (int i=lo; i<hi; i++) s += deg[k*N+i];
    __shared__ int ps[T];
    ps[t] = s;
    __syncthreads();
    for (int off=1; off<T; off<<=1){
        int v = (t>=off) ? ps[t-off] : 0;
        __syncthreads();
        ps[t] += v;
        __syncthreads();
    }
    int run = (t>0) ? ps[t-1] : 0;
    for (int i=lo; i<hi; i++){
        rowptr[k*(N+1)+i] = run;
        dcur[k*N+i] = run;
        run += deg[k*N+i];
    }
    if (t == 0) rowptr[k*(N+1)+N] = E;
}

__global__ void fill_kernel(const int* __restrict__ ke, int* __restrict__ dcur,
                            int* __restrict__ csrc, int E, int N)
{
    int i = blockIdx.x*blockDim.x+threadIdx.x;
    if (i >= KS*E) return;
    int k = i/E, e = i - k*E;
    int s = ke[(size_t)(k*2)*E + e];
    int d = ke[(size_t)(k*2+1)*E + e];
    int pos = atomicAdd(&dcur[k*N + d], 1);
    csrc[k*E + pos] = s;
}

// aggregate: agg[k][n] = (1+eps)*f(In[n]) + sum_j f(In[src_j]),
// f = identity (useBN=0) or relu(v*scaleD+shiftD). Output = split bf16 planes.
__global__ void aggregate_kernel(const float* __restrict__ In,
                                 const int* __restrict__ rowptr, const int* __restrict__ csrc,
                                 const float* __restrict__ epsp,
                                 const float* __restrict__ scale, const float* __restrict__ shift,
                                 int useBN,
                                 __nv_bfloat16* __restrict__ AggH, __nv_bfloat16* __restrict__ AggL,
                                 int N, int E)
{
    int gw = (blockIdx.x*blockDim.x + threadIdx.x) >> 5;
    int lane = threadIdx.x & 31;
    int k = blockIdx.y;
    if (gw >= N) return;
    float4 sc = make_float4(1.f,1.f,1.f,1.f), sh = make_float4(0.f,0.f,0.f,0.f);
    if (useBN){ sc = ((const float4*)scale)[lane]; sh = ((const float4*)shift)[lane]; }

    auto fx = [&](float4 v) -> float4 {
        if (useBN){
            v.x = fmaxf(fmaf(v.x, sc.x, sh.x), 0.f);
            v.y = fmaxf(fmaf(v.y, sc.y, sh.y), 0.f);
            v.z = fmaxf(fmaf(v.z, sc.z, sh.z), 0.f);
            v.w = fmaxf(fmaf(v.w, sc.w, sh.w), 0.f);
        }
        return v;
    };

    float se = 1.0f + epsp[0];
    float4 c = fx(__ldg((const float4*)(In + (size_t)gw*D) + lane));
    c.x*=se; c.y*=se; c.z*=se; c.w*=se;

    const int* cs = csrc + (size_t)k*E;
    int lo = __ldg(rowptr + k*(N+1) + gw);
    int hi = __ldg(rowptr + k*(N+1) + gw + 1);
    int j = lo;
    for (; j + 4 <= hi; j += 4){
        int s0=__ldg(cs+j), s1=__ldg(cs+j+1), s2=__ldg(cs+j+2), s3=__ldg(cs+j+3);
        float4 v0=fx(__ldg((const float4*)(In+(size_t)s0*D)+lane));
        float4 v1=fx(__ldg((const float4*)(In+(size_t)s1*D)+lane));
        float4 v2=fx(__ldg((const float4*)(In+(size_t)s2*D)+lane));
        float4 v3=fx(__ldg((const float4*)(In+(size_t)s3*D)+lane));
        c.x += (v0.x+v1.x)+(v2.x+v3.x);
        c.y += (v0.y+v1.y)+(v2.y+v3.y);
        c.z += (v0.z+v1.z)+(v2.z+v3.z);
        c.w += (v0.w+v1.w)+(v2.w+v3.w);
    }
    for (; j < hi; j++){
        int s = __ldg(cs+j);
        float4 v = fx(__ldg((const float4*)(In+(size_t)s*D)+lane));
        c.x+=v.x; c.y+=v.y; c.z+=v.z; c.w+=v.w;
    }
    uint2 hp, lp;
    split4(c, hp, lp);
    size_t base = (size_t)k*NPAD*D + (size_t)gw*D;
    *(uint2*)(AggH + base + lane*4) = hp;
    *(uint2*)(AggL + base + lane*4) = lp;
}

// ---------------------------------------------------------------------------
// Pure-bf16 pipelined HMMA GEMM. KEY CHANGE vs R10: the three plane combos
// are issued as three separate full (m,n) sweeps so consecutive MMAs never
// share an accumulator (dependency distance 16 instead of 1).
// ---------------------------------------------------------------------------
template <int KTOT, int NTOT, bool CZ>
__global__ __launch_bounds__(256, 2) void bgemm_kernel(
    const __nv_bfloat16* __restrict__ Ahp, const __nv_bfloat16* __restrict__ Alp,
    const __nv_bfloat16* __restrict__ Bhp, const __nv_bfloat16* __restrict__ Blp,
    const float* __restrict__ bias,
    float* __restrict__ C, int M)
{
    extern __shared__ __align__(16) char dynsm[];
    __nv_bfloat16* sAh = (__nv_bfloat16*)(dynsm+OFF_AH);   // [2][128][40]
    __nv_bfloat16* sAl = (__nv_bfloat16*)(dynsm+OFF_AL);
    __nv_bfloat16* sBh = (__nv_bfloat16*)(dynsm+OFF_BH);   // [2][32][136]
    __nv_bfloat16* sBl = (__nv_bfloat16*)(dynsm+OFF_BL);

    const int tid=threadIdx.x, wid=tid>>5, lane=tid&31;
    const int wm=wid>>1, wn=wid&1;
    const int rowBase=blockIdx.x*BM, colBase=blockIdx.y*BN;

    const __nv_bfloat16* Ah = Ahp;
    const __nv_bfloat16* Al = Alp;
    float* Cp = C;
    if (CZ){
        const int z = blockIdx.z;
        Ah += (size_t)z*NPAD*KTOT;
        Al += (size_t)z*NPAD*KTOT;
        Cp += (size_t)z*NPAD*NTOT;
    }

    const int ar=tid>>1, ahh=tid&1;
    const int br=tid>>4, bcv=tid&15;

    auto issue_tile=[&](int t,int s){
        const int kk=t*BK;
        __nv_bfloat16* ahDst=sAh+s*(128*40);
        __nv_bfloat16* alDst=sAl+s*(128*40);
#pragma unroll
        for (int j=0;j<2;j++){
            int col = ahh*16 + j*8;
            cp16(ahDst+ar*40+col, Ah+(size_t)(rowBase+ar)*KTOT+kk+col);
            cp16(alDst+ar*40+col, Al+(size_t)(rowBase+ar)*KTOT+kk+col);
        }
        __nv_bfloat16* bhDst=sBh+s*(32*136);
        __nv_bfloat16* blDst=sBl+s*(32*136);
#pragma unroll
        for (int p=0;p<2;p++){
            int r=br+p*16;
            cp16(bhDst+r*136+bcv*8, Bhp+(size_t)(kk+r)*NTOT+colBase+bcv*8);
            cp16(blDst+r*136+bcv*8, Blp+(size_t)(kk+r)*NTOT+colBase+bcv*8);
        }
    };

    issue_tile(0,0);
    asm volatile("cp.async.commit_group;":::"memory");

    float acc[2][8][4];
#pragma unroll
    for (int m=0;m<2;m++)
#pragma unroll
        for (int n=0;n<8;n++)
#pragma unroll
            for (int q=0;q<4;q++) acc[m][n][q]=0.f;

    const int ktiles=KTOT/BK;
    for (int t=0;t<ktiles;t++){
        const int s=t&1;
        asm volatile("cp.async.wait_group 0;":::"memory");
        __syncthreads();
        if (t+1<ktiles){ issue_tile(t+1,s^1); asm volatile("cp.async.commit_group;":::"memory"); }

        const __nv_bfloat16 *ah_s=sAh+s*(128*40), *al_s=sAl+s*(128*40);
        const __nv_bfloat16 *bh_s=sBh+s*(32*136), *bl_s=sBl+s*(32*136);
#pragma unroll
        for (int kb=0;kb<BK/16;kb++){
            uint32_t ah[2][4], al[2][4], bf[8][2];
#pragma unroll
            for (int m=0;m<2;m++){
                int row=wm*32+m*16+(lane&15), col=kb*16+(lane>>4)*8;
                ldsm_x4(ah[m], smem_u32(ah_s+row*40+col));
                ldsm_x4(al[m], smem_u32(al_s+row*40+col));
            }
#pragma unroll
            for (int nb=0;nb<4;nb++){
                int row=kb*16+(lane&15), col=wn*64+nb*16+(lane>>4)*8;
                uint32_t tr[4];
                ldsm_x4t(tr, smem_u32(bh_s+row*136+col));
                bf[nb*2][0]=tr[0]; bf[nb*2][1]=tr[1];
                bf[nb*2+1][0]=tr[2]; bf[nb*2+1][1]=tr[3];
            }
            // combo 1: Ah*Bh — 16 independent accumulators back-to-back
#pragma unroll
            for (int m=0;m<2;m++)
#pragma unroll
                for (int n=0;n<8;n++) mma16816(acc[m][n],ah[m],bf[n]);
            // combo 2: Al*Bh — each acc revisited 16 MMAs later
#pragma unroll
            for (int m=0;m<2;m++)
#pragma unroll
                for (int n=0;n<8;n++) mma16816(acc[m][n],al[m],bf[n]);
            // combo 3: Ah*Bl (reload bf from the low B plane)
#pragma unroll
            for (int nb=0;nb<4;nb++){
                int row=kb*16+(lane&15), col=wn*64+nb*16+(lane>>4)*8;
                uint32_t tr[4];
                ldsm_x4t(tr, smem_u32(bl_s+row*136+col));
                bf[nb*2][0]=tr[0]; bf[nb*2][1]=tr[1];
                bf[nb*2+1][0]=tr[2]; bf[nb*2+1][1]=tr[3];
            }
#pragma unroll
            for (int m=0;m<2;m++)
#pragma unroll
                for (int n=0;n<8;n++) mma16816(acc[m][n],ah[m],bf[n]);
        }
    }

#pragma unroll
    for (int m=0;m<2;m++){
        int rbase=rowBase+wm*32+m*16+(lane>>2);
#pragma unroll
        for (int half=0;half<2;half++){
            int rr=rbase+half*8;
            if (rr<M){
#pragma unroll
                for (int n=0;n<8;n++){
                    int c=colBase+wn*64+n*8+(lane&3)*2;
                    float2 o;
                    o.x=acc[m][n][half*2+0]+bias[c];
                    o.y=acc[m][n][half*2+1]+bias[c+1];
                    *(float2*)(Cp+(size_t)rr*NTOT+c)=o;
                }
            }
        }
    }
}

// zc = sum_k aw[k] * relu( y1_k * scale_k + shift_k )  -> split bf16 planes
__global__ void combine_kernel(const float* __restrict__ Y1, const float* __restrict__ scale,
                               const float* __restrict__ shift, const float* __restrict__ aw,
                               __nv_bfloat16* __restrict__ ZcH, __nv_bfloat16* __restrict__ ZcL,
                               int n4)
{
    int i = blockIdx.x*blockDim.x+threadIdx.x;
    if (i >= n4) return;
    int c4 = i & 63;
    float4 acc = make_float4(0.f,0.f,0.f,0.f);
    const int zs = NPAD*(D2/4);
#pragma unroll
    for (int k=0;k<KS;k++){
        float a = __ldg(aw+k);
        float4 v  = __ldg((const float4*)Y1 + (size_t)k*zs + i);
        float4 sc = __ldg((const float4*)(scale+k*D2)+c4);
        float4 sh = __ldg((const float4*)(shift+k*D2)+c4);
        acc.x += a*fmaxf(fmaf(v.x,sc.x,sh.x),0.f);
        acc.y += a*fmaxf(fmaf(v.y,sc.y,sh.y),0.f);
        acc.z += a*fmaxf(fmaf(v.z,sc.z,sh.z),0.f);
        acc.w += a*fmaxf(fmaf(v.w,sc.w,sh.w),0.f);
    }
    uint2 hp, lp;
    split4(acc, hp, lp);
    ((uint2*)ZcH)[i] = hp;
    ((uint2*)ZcL)[i] = lp;
}

__global__ void colstats_kernel(const float* __restrict__ X, int M, int C, size_t zstride,
                                float* __restrict__ s, float* __restrict__ q)
{
    int z = blockIdx.y;
    X += (size_t)z*zstride; s += (size_t)z*C; q += (size_t)z*C;
    int c = threadIdx.x;
    float ps=0.f, pq=0.f;
    for (int r=blockIdx.x; r<M; r+=gridDim.x){
        float v = X[(size_t)r*C+c];
        ps += v; pq += v*v;
    }
    atomicAdd(&s[c],ps); atomicAdd(&q[c],pq);
}

__global__ void finalize_kernel(const float* __restrict__ s, const float* __restrict__ q,
                                const float* __restrict__ g, const float* __restrict__ b,
                                float* __restrict__ scale, float* __restrict__ shift,
                                float invN, int C)
{
    int k = blockIdx.x, c = threadIdx.x;
    float mu = s[k*C+c]*invN;
    float var = q[k*C+c]*invN - mu*mu;
    float rstd = rsqrtf(var+1e-5f);
    float sc = rstd*g[c];
    scale[k*C+c] = sc;
    shift[k*C+c] = b[c]-mu*sc;
}

__global__ void bnrelu_kernel(const float* __restrict__ X, const float* __restrict__ scale,
                              const float* __restrict__ shift, float* __restrict__ Out, int n4)
{
    int i = blockIdx.x*blockDim.x+threadIdx.x;
    if (i >= n4) return;
    int c4 = i & 31;
    float4 v  = ((const float4*)X)[i];
    float4 sc = ((const float4*)scale)[c4];
    float4 sh = ((const float4*)shift)[c4];
    v.x=fmaxf(fmaf(v.x,sc.x,sh.x),0.f);
    v.y=fmaxf(fmaf(v.y,sc.y,sh.y),0.f);
    v.z=fmaxf(fmaf(v.z,sc.z,sh.z),0.f);
    v.w=fmaxf(fmaf(v.w,sc.w,sh.w),0.f);
    ((float4*)Out)[i] = v;
}

// ---------------------------------------------------------------------------
extern "C" void kernel_launch(void* const* d_in, const int* in_sizes, int n_in,
                              void* d_out, int out_size)
{
    const int*   x     = (const int*)  d_in[0];
    const int*   ke    = (const int*)  d_in[1];
    const float* emb   = (const float*)d_in[2];
    const float* W1    = (const float*)d_in[3];
    const float* b1    = (const float*)d_in[4];
    const float* g1    = (const float*)d_in[5];
    const float* be1   = (const float*)d_in[6];
    const float* W2    = (const float*)d_in[7];
    const float* b2    = (const float*)d_in[8];
    const float* eps   = (const float*)d_in[9];
    const float* alpha = (const float*)d_in[10];
    const float* bn_g  = (const float*)d_in[11];
    const float* bn_b  = (const float*)d_in[12];

    const int N = in_sizes[0]/NFEAT;
    const int E = in_sizes[1]/(KS*2);
    const int n4  = N*(D/4);
    const int n4b = N*(D2/4);
    const int nTilesM = (N+BM-1)/BM;

    float *p_h,*p_y1,*p_hacc,*p_sum,*p_sq,*p_scale,*p_shift,*p_scaleD,*p_shiftD,*p_aw;
    __nv_bfloat16 *p_aggH,*p_aggL,*p_zcH,*p_zcL,*p_w1h,*p_w1l,*p_w2h,*p_w2l;
    int *p_deg,*p_dcur,*p_rowptr,*p_csrc;
    cudaGetSymbolAddress((void**)&p_h,g_h);
    cudaGetSymbolAddress((void**)&p_y1,g_y1);
    cudaGetSymbolAddress((void**)&p_hacc,g_hacc);
    cudaGetSymbolAddress((void**)&p_aggH,g_aggH);
    cudaGetSymbolAddress((void**)&p_aggL,g_aggL);
    cudaGetSymbolAddress((void**)&p_zcH,g_zcH);
    cudaGetSymbolAddress((void**)&p_zcL,g_zcL);
    cudaGetSymbolAddress((void**)&p_sum,g_sum);
    cudaGetSymbolAddress((void**)&p_sq,g_sq);
    cudaGetSymbolAddress((void**)&p_scale,g_scale);
    cudaGetSymbolAddress((void**)&p_shift,g_shift);
    cudaGetSymbolAddress((void**)&p_scaleD,g_scaleD);
    cudaGetSymbolAddress((void**)&p_shiftD,g_shiftD);
    cudaGetSymbolAddress((void**)&p_aw,g_aw);
    cudaGetSymbolAddress((void**)&p_w1h,g_W1h);
    cudaGetSymbolAddress((void**)&p_w1l,g_W1l);
    cudaGetSymbolAddress((void**)&p_w2h,g_W2h);
    cudaGetSymbolAddress((void**)&p_w2l,g_W2l);
    cudaGetSymbolAddress((void**)&p_deg,g_deg);
    cudaGetSymbolAddress((void**)&p_dcur,g_dcur);
    cudaGetSymbolAddress((void**)&p_rowptr,g_rowptr);
    cudaGetSymbolAddress((void**)&p_csrc,g_csrc);

    cudaFuncSetAttribute(bgemm_kernel<D,  D2, true >,
                         cudaFuncAttributeMaxDynamicSharedMemorySize, SMEM_BYTES);
    cudaFuncSetAttribute(bgemm_kernel<D2, D,  false>,
                         cudaFuncAttributeMaxDynamicSharedMemorySize, SMEM_BYTES);

    const float invN = 1.0f/(float)N;

    {
        int tot = 2*LAY*D*D2;
        wsplit_kernel<<<(tot+255)/256, 256>>>(W1, W2, p_w1h, p_w1l, p_w2h, p_w2l);
    }
    // CSR build (once; edge sets constant across layers)
    cudaMemsetAsync(p_deg, 0, (size_t)KS*N*sizeof(int));
    hist_kernel<<<(KS*E+255)/256, 256>>>(ke, p_deg, E, N);
    scan_kernel<<<KS, 1024>>>(p_deg, p_rowptr, p_dcur, N, E);
    fill_kernel<<<(KS*E+255)/256, 256>>>(ke, p_dcur, p_csrc, E, N);

    embed_kernel<<<(N*32+255)/256, 256>>>(x, emb, p_h, N);

    for (int l = 0; l < LAY; l++){
        softmax3_kernel<<<1,1>>>(alpha+l*KS, p_aw);

        const float* inb = (l == 0) ? p_h : p_hacc;
        aggregate_kernel<<<dim3((N*32+255)/256, KS), 256>>>(
            inb, p_rowptr, p_csrc, eps+l, p_scaleD, p_shiftD, (l>0)?1:0,
            p_aggH, p_aggL, N, E);

        bgemm_kernel<D, D2, true><<<dim3(nTilesM, 2, KS), 256, SMEM_BYTES>>>(
            p_aggH, p_aggL, p_w1h+(size_t)l*D*D2, p_w1l+(size_t)l*D*D2, b1+l*D2, p_y1, N);

        cudaMemsetAsync(p_sum, 0, KS*D2*sizeof(float));
        cudaMemsetAsync(p_sq,  0, KS*D2*sizeof(float));
        colstats_kernel<<<dim3(1024,KS), D2>>>(p_y1, N, D2, (size_t)NPAD*D2, p_sum, p_sq);
        finalize_kernel<<<KS, D2>>>(p_sum, p_sq, g1+l*D2, be1+l*D2, p_scale, p_shift, invN, D2);

        combine_kernel<<<(n4b+255)/256, 256>>>(p_y1, p_scale, p_shift, p_aw, p_zcH, p_zcL, n4b);

        bgemm_kernel<D2, D, false><<<dim3(nTilesM,1,1), 256, SMEM_BYTES>>>(
            p_zcH, p_zcL, p_w2h+(size_t)l*D2*D, p_w2l+(size_t)l*D2*D, b2+l*D, p_hacc, N);

        cudaMemsetAsync(p_sum, 0, D*sizeof(float));
        cudaMemsetAsync(p_sq,  0, D*sizeof(float));
        colstats_kernel<<<dim3(2048,1), D>>>(p_hacc, N, D, 0, p_sum, p_sq);
        finalize_kernel<<<1, D>>>(p_sum, p_sq, bn_g+l*D, bn_b+l*D, p_scaleD, p_shiftD, invN, D);

        if (l == LAY-1)
            bnrelu_kernel<<<(n4+255)/256, 256>>>(p_hacc, p_scaleD, p_shiftD, (float*)d_out, n4);
    }
}

// round 12
// speedup vs baseline: 1.0598x; 1.0598x over previous
#include <cuda_runtime.h>
#include <cuda_bf16.h>
#include <cstdint>

namespace {
constexpr int D=128, D2=256, NFEAT=9, VOC=100, KS=3, LAY=3, NPAD=100096;
constexpr int EMAX=600000;
constexpr int BM=128, BN=128, BK=32;
constexpr int OFF_AH=0, OFF_AL=20480, OFF_BH=40960, OFF_BL=58368;
constexpr int SMEM_BYTES=75776;
}

__device__ float g_hW  [NPAD * D2];                 // h @ W1 (no bias)
__device__ float g_y1  [KS * NPAD * D2];
__device__ float g_hacc[NPAD * D];
__device__ __align__(16) __nv_bfloat16 g_hH[NPAD * D];
__device__ __align__(16) __nv_bfloat16 g_hL[NPAD * D];
__device__ __align__(16) __nv_bfloat16 g_zcH[NPAD * D2];
__device__ __align__(16) __nv_bfloat16 g_zcL[NPAD * D2];
__device__ float g_sum  [KS * D2];
__device__ float g_sq   [KS * D2];
__device__ float g_scale[KS * D2];
__device__ float g_shift[KS * D2];
__device__ float g_scaleD[D];
__device__ float g_shiftD[D];
__device__ float g_aw   [KS];
__device__ float g_zero [D2];                       // zero bias for gemm1
__device__ __align__(16) __nv_bfloat16 g_W1h[LAY * D * D2];
__device__ __align__(16) __nv_bfloat16 g_W1l[LAY * D * D2];
__device__ __align__(16) __nv_bfloat16 g_W2h[LAY * D2 * D];
__device__ __align__(16) __nv_bfloat16 g_W2l[LAY * D2 * D];
// CSR scratch (built once per launch)
__device__ int g_deg   [KS * NPAD];
__device__ int g_dcur  [KS * NPAD];
__device__ int g_rowptr[KS * (NPAD + 1)];
__device__ int g_csrc  [KS * EMAX];

// ---------------- PTX helpers ----------------
__device__ __forceinline__ uint32_t smem_u32(const void* p){return (uint32_t)__cvta_generic_to_shared(p);}
__device__ __forceinline__ void ldsm_x4(uint32_t r[4], uint32_t a){
    asm volatile("ldmatrix.sync.aligned.m8n8.x4.shared.b16 {%0,%1,%2,%3},[%4];"
                 :"=r"(r[0]),"=r"(r[1]),"=r"(r[2]),"=r"(r[3]):"r"(a));
}
__device__ __forceinline__ void ldsm_x4t(uint32_t r[4], uint32_t a){
    asm volatile("ldmatrix.sync.aligned.m8n8.x4.trans.shared.b16 {%0,%1,%2,%3},[%4];"
                 :"=r"(r[0]),"=r"(r[1]),"=r"(r[2]),"=r"(r[3]):"r"(a));
}
__device__ __forceinline__ void mma16816(float c[4], const uint32_t a[4], const uint32_t* b){
    asm volatile("mma.sync.aligned.m16n8k16.row.col.f32.bf16.bf16.f32 "
                 "{%0,%1,%2,%3},{%4,%5,%6,%7},{%8,%9},{%0,%1,%2,%3};"
                 :"+f"(c[0]),"+f"(c[1]),"+f"(c[2]),"+f"(c[3])
                 :"r"(a[0]),"r"(a[1]),"r"(a[2]),"r"(a[3]),"r"(b[0]),"r"(b[1]));
}
__device__ __forceinline__ void cp16(void* d, const void* s){
    asm volatile("cp.async.cg.shared.global [%0],[%1],16;"::"r"(smem_u32(d)),"l"(s):"memory");
}
__device__ __forceinline__ uint32_t bf2(__nv_bfloat16 a, __nv_bfloat16 b){
    __nv_bfloat162 t; t.x=a; t.y=b; return *reinterpret_cast<uint32_t*>(&t);
}
__device__ __forceinline__ void split4(float4 v, uint2& hp, uint2& lp){
    __nv_bfloat16 h0=__float2bfloat16(v.x), h1=__float2bfloat16(v.y);
    __nv_bfloat16 h2=__float2bfloat16(v.z), h3=__float2bfloat16(v.w);
    hp = make_uint2(bf2(h0,h1), bf2(h2,h3));
    lp = make_uint2(
        bf2(__float2bfloat16(v.x-__bfloat162float(h0)), __float2bfloat16(v.y-__bfloat162float(h1))),
        bf2(__float2bfloat16(v.z-__bfloat162float(h2)), __float2bfloat16(v.w-__bfloat162float(h3))));
}

// ---------------- small kernels ----------------
// embed -> split bf16 planes directly
__global__ void embed_split_kernel(const int* __restrict__ x, const float* __restrict__ emb,
                                   __nv_bfloat16* __restrict__ hH, __nv_bfloat16* __restrict__ hL,
                                   int N)
{
    int gt = blockIdx.x*blockDim.x+threadIdx.x;
    int node = gt>>5, lane = gt&31;
    if (node >= N) return;
    float4 acc = make_float4(0.f,0.f,0.f,0.f);
#pragma unroll
    for (int f=0; f<NFEAT; f++){
        int idx = x[node*NFEAT+f];
        float4 v = ((const float4*)(emb + ((size_t)f*VOC+idx)*D))[lane];
        acc.x+=v.x; acc.y+=v.y; acc.z+=v.z; acc.w+=v.w;
    }
    uint2 hp, lp;
    split4(acc, hp, lp);
    *(uint2*)(hH + (size_t)node*D + lane*4) = hp;
    *(uint2*)(hL + (size_t)node*D + lane*4) = lp;
}

// inter-layer: h = relu(BN(hacc)) -> split bf16 planes
__global__ void bnrelu_split_kernel(const float* __restrict__ X,
                                    const float* __restrict__ scale, const float* __restrict__ shift,
                                    __nv_bfloat16* __restrict__ hH, __nv_bfloat16* __restrict__ hL,
                                    int n4)
{
    int i = blockIdx.x*blockDim.x+threadIdx.x;
    if (i >= n4) return;
    int c4 = i & 31;
    float4 v  = ((const float4*)X)[i];
    float4 sc = ((const float4*)scale)[c4];
    float4 sh = ((const float4*)shift)[c4];
    v.x=fmaxf(fmaf(v.x,sc.x,sh.x),0.f);
    v.y=fmaxf(fmaf(v.y,sc.y,sh.y),0.f);
    v.z=fmaxf(fmaf(v.z,sc.z,sh.z),0.f);
    v.w=fmaxf(fmaf(v.w,sc.w,sh.w),0.f);
    uint2 hp, lp;
    split4(v, hp, lp);
    ((uint2*)hH)[i] = hp;
    ((uint2*)hL)[i] = lp;
}

__global__ void softmax3_kernel(const float* __restrict__ alpha, float* __restrict__ a)
{
    float a0=alpha[0],a1=alpha[1],a2=alpha[2];
    float m=fmaxf(a0,fmaxf(a1,a2));
    float e0=expf(a0-m),e1=expf(a1-m),e2=expf(a2-m);
    float inv=1.f/(e0+e1+e2);
    a[0]=e0*inv; a[1]=e1*inv; a[2]=e2*inv;
}

__global__ void wsplit_kernel(const float* __restrict__ W1, const float* __restrict__ W2,
                              __nv_bfloat16* __restrict__ w1h, __nv_bfloat16* __restrict__ w1l,
                              __nv_bfloat16* __restrict__ w2h, __nv_bfloat16* __restrict__ w2l)
{
    int i = blockIdx.x*blockDim.x+threadIdx.x;
    const int tot = LAY*D*D2;
    if (i < tot){
        float v = W1[i];
        __nv_bfloat16 h = __float2bfloat16(v);
        w1h[i] = h;
        w1l[i] = __float2bfloat16(v-__bfloat162float(h));
    } else if (i < 2*tot){
        int j = i-tot;
        float v = W2[j];
        __nv_bfloat16 h = __float2bfloat16(v);
        w2h[j] = h;
        w2l[j] = __float2bfloat16(v-__bfloat162float(h));
    }
}

// ---------------- CSR build ----------------
__global__ void hist_kernel(const int* __restrict__ ke, int* __restrict__ deg, int E, int N)
{
    int i = blockIdx.x*blockDim.x+threadIdx.x;
    if (i >= KS*E) return;
    int k = i/E, e = i - k*E;
    int d = ke[(size_t)(k*2+1)*E + e];
    atomicAdd(&deg[k*N + d], 1);
}

__global__ void scan_kernel(const int* __restrict__ deg, int* __restrict__ rowptr,
                            int* __restrict__ dcur, int N, int E)
{
    const int T = 1024;
    int k = blockIdx.x, t = threadIdx.x;
    int chunk = (N + T - 1)/T;
    int lo = t*chunk, hi = min(lo+chunk, N);
    int s = 0;
    for (int i=lo; i<hi; i++) s += deg[k*N+i];
    __shared__ int ps[T];
    ps[t] = s;
    __syncthreads();
    for (int off=1; off<T; off<<=1){
        int v = (t>=off) ? ps[t-off] : 0;
        __syncthreads();
        ps[t] += v;
        __syncthreads();
    }
    int run = (t>0) ? ps[t-1] : 0;
    for (int i=lo; i<hi; i++){
        rowptr[k*(N+1)+i] = run;
        dcur[k*N+i] = run;
        run += deg[k*N+i];
    }
    if (t == 0) rowptr[k*(N+1)+N] = E;
}

__global__ void fill_kernel(const int* __restrict__ ke, int* __restrict__ dcur,
                            int* __restrict__ csrc, int E, int N)
{
    int i = blockIdx.x*blockDim.x+threadIdx.x;
    if (i >= KS*E) return;
    int k = i/E, e = i - k*E;
    int s = ke[(size_t)(k*2)*E + e];
    int d = ke[(size_t)(k*2+1)*E + e];
    int pos = atomicAdd(&dcur[k*N + d], 1);
    csrc[k*E + pos] = s;
}

// y1_k[n] = (1+eps)*hW[n] + sum_{src} hW[src] + b1   (256-dim, fp32)
// one warp per (node, k); lane handles float4 columns lane and lane+32.
__global__ void aggregate256_kernel(const float* __restrict__ hW,
                                    const int* __restrict__ rowptr, const int* __restrict__ csrc,
                                    const float* __restrict__ epsp, const float* __restrict__ b1,
                                    float* __restrict__ Y1, int N, int E)
{
    int gw = (blockIdx.x*blockDim.x + threadIdx.x) >> 5;
    int lane = threadIdx.x & 31;
    int k = blockIdx.y;
    if (gw >= N) return;
    float se = 1.0f + epsp[0];
    const float4* row = (const float4*)(hW + (size_t)gw*D2);
    float4 c0 = __ldg(row + lane);
    float4 c1 = __ldg(row + lane + 32);
    c0.x*=se; c0.y*=se; c0.z*=se; c0.w*=se;
    c1.x*=se; c1.y*=se; c1.z*=se; c1.w*=se;

    const int* cs = csrc + (size_t)k*E;
    int lo = __ldg(rowptr + k*(N+1) + gw);
    int hi = __ldg(rowptr + k*(N+1) + gw + 1);
    int j = lo;
    for (; j + 2 <= hi; j += 2){
        int s0=__ldg(cs+j), s1=__ldg(cs+j+1);
        const float4* r0 = (const float4*)(hW + (size_t)s0*D2);
        const float4* r1 = (const float4*)(hW + (size_t)s1*D2);
        float4 a0=__ldg(r0+lane), a1=__ldg(r0+lane+32);
        float4 b0=__ldg(r1+lane), b1v=__ldg(r1+lane+32);
        c0.x += a0.x+b0.x; c0.y += a0.y+b0.y; c0.z += a0.z+b0.z; c0.w += a0.w+b0.w;
        c1.x += a1.x+b1v.x; c1.y += a1.y+b1v.y; c1.z += a1.z+b1v.z; c1.w += a1.w+b1v.w;
    }
    for (; j < hi; j++){
        int s = __ldg(cs+j);
        const float4* r = (const float4*)(hW + (size_t)s*D2);
        float4 a0=__ldg(r+lane), a1=__ldg(r+lane+32);
        c0.x+=a0.x; c0.y+=a0.y; c0.z+=a0.z; c0.w+=a0.w;
        c1.x+=a1.x; c1.y+=a1.y; c1.z+=a1.z; c1.w+=a1.w;
    }
    float4 bb0 = __ldg((const float4*)b1 + lane);
    float4 bb1 = __ldg((const float4*)b1 + lane + 32);
    c0.x+=bb0.x; c0.y+=bb0.y; c0.z+=bb0.z; c0.w+=bb0.w;
    c1.x+=bb1.x; c1.y+=bb1.y; c1.z+=bb1.z; c1.w+=bb1.w;

    float4* out = (float4*)(Y1 + (size_t)k*NPAD*D2 + (size_t)gw*D2);
    out[lane] = c0;
    out[lane+32] = c1;
}

// ---------------------------------------------------------------------------
// Pure-bf16 pipelined HMMA GEMM (2 planes, 3 combos).
// ---------------------------------------------------------------------------
template <int KTOT, int NTOT>
__global__ __launch_bounds__(256, 2) void bgemm_kernel(
    const __nv_bfloat16* __restrict__ Ahp, const __nv_bfloat16* __restrict__ Alp,
    const __nv_bfloat16* __restrict__ Bhp, const __nv_bfloat16* __restrict__ Blp,
    const float* __restrict__ bias,
    float* __restrict__ C, int M)
{
    extern __shared__ __align__(16) char dynsm[];
    __nv_bfloat16* sAh = (__nv_bfloat16*)(dynsm+OFF_AH);
    __nv_bfloat16* sAl = (__nv_bfloat16*)(dynsm+OFF_AL);
    __nv_bfloat16* sBh = (__nv_bfloat16*)(dynsm+OFF_BH);
    __nv_bfloat16* sBl = (__nv_bfloat16*)(dynsm+OFF_BL);

    const int tid=threadIdx.x, wid=tid>>5, lane=tid&31;
    const int wm=wid>>1, wn=wid&1;
    const int rowBase=blockIdx.x*BM, colBase=blockIdx.y*BN;

    const int ar=tid>>1, ahh=tid&1;
    const int br=tid>>4, bcv=tid&15;

    auto issue_tile=[&](int t,int s){
        const int kk=t*BK;
        __nv_bfloat16* ahDst=sAh+s*(128*40);
        __nv_bfloat16* alDst=sAl+s*(128*40);
#pragma unroll
        for (int j=0;j<2;j++){
            int col = ahh*16 + j*8;
            cp16(ahDst+ar*40+col, Ahp+(size_t)(rowBase+ar)*KTOT+kk+col);
            cp16(alDst+ar*40+col, Alp+(size_t)(rowBase+ar)*KTOT+kk+col);
        }
        __nv_bfloat16* bhDst=sBh+s*(32*136);
        __nv_bfloat16* blDst=sBl+s*(32*136);
#pragma unroll
        for (int p=0;p<2;p++){
            int r=br+p*16;
            cp16(bhDst+r*136+bcv*8, Bhp+(size_t)(kk+r)*NTOT+colBase+bcv*8);
            cp16(blDst+r*136+bcv*8, Blp+(size_t)(kk+r)*NTOT+colBase+bcv*8);
        }
    };

    issue_tile(0,0);
    asm volatile("cp.async.commit_group;":::"memory");

    float acc[2][8][4];
#pragma unroll
    for (int m=0;m<2;m++)
#pragma unroll
        for (int n=0;n<8;n++)
#pragma unroll
            for (int q=0;q<4;q++) acc[m][n][q]=0.f;

    const int ktiles=KTOT/BK;
    for (int t=0;t<ktiles;t++){
        const int s=t&1;
        asm volatile("cp.async.wait_group 0;":::"memory");
        __syncthreads();
        if (t+1<ktiles){ issue_tile(t+1,s^1); asm volatile("cp.async.commit_group;":::"memory"); }

        const __nv_bfloat16 *ah_s=sAh+s*(128*40), *al_s=sAl+s*(128*40);
        const __nv_bfloat16 *bh_s=sBh+s*(32*136), *bl_s=sBl+s*(32*136);
#pragma unroll
        for (int kb=0;kb<BK/16;kb++){
            uint32_t ah[2][4], al[2][4], bf[8][2];
#pragma unroll
            for (int m=0;m<2;m++){
                int row=wm*32+m*16+(lane&15), col=kb*16+(lane>>4)*8;
                ldsm_x4(ah[m], smem_u32(ah_s+row*40+col));
                ldsm_x4(al[m], smem_u32(al_s+row*40+col));
            }
#pragma unroll
            for (int nb=0;nb<4;nb++){
                int row=kb*16+(lane&15), col=wn*64+nb*16+(lane>>4)*8;
                uint32_t tr[4];
                ldsm_x4t(tr, smem_u32(bh_s+row*136+col));
                bf[nb*2][0]=tr[0]; bf[nb*2][1]=tr[1];
                bf[nb*2+1][0]=tr[2]; bf[nb*2+1][1]=tr[3];
            }
#pragma unroll
            for (int m=0;m<2;m++)
#pragma unroll
                for (int n=0;n<8;n++) mma16816(acc[m][n],ah[m],bf[n]);
#pragma unroll
            for (int m=0;m<2;m++)
#pragma unroll
                for (int n=0;n<8;n++) mma16816(acc[m][n],al[m],bf[n]);
#pragma unroll
            for (int nb=0;nb<4;nb++){
                int row=kb*16+(lane&15), col=wn*64+nb*16+(lane>>4)*8;
                uint32_t tr[4];
                ldsm_x4t(tr, smem_u32(bl_s+row*136+col));
                bf[nb*2][0]=tr[0]; bf[nb*2][1]=tr[1];
                bf[nb*2+1][0]=tr[2]; bf[nb*2+1][1]=tr[3];
            }
#pragma unroll
            for (int m=0;m<2;m++)
#pragma unroll
                for (int n=0;n<8;n++) mma16816(acc[m][n],ah[m],bf[n]);
        }
    }

#pragma unroll
    for (int m=0;m<2;m++){
        int rbase=rowBase+wm*32+m*16+(lane>>2);
#pragma unroll
        for (int half=0;half<2;half++){
            int rr=rbase+half*8;
            if (rr<M){
#pragma unroll
                for (int n=0;n<8;n++){
                    int c=colBase+wn*64+n*8+(lane&3)*2;
                    float2 o;
                    o.x=acc[m][n][half*2+0]+bias[c];
                    o.y=acc[m][n][half*2+1]+bias[c+1];
                    *(float2*)(C+(size_t)rr*NTOT+c)=o;
                }
            }
        }
    }
}

// zc = sum_k aw[k] * relu( y1_k * scale_k + shift_k )  -> split bf16 planes
__global__ void combine_kernel(const float* __restrict__ Y1, const float* __restrict__ scale,
                               const float* __restrict__ shift, const float* __restrict__ aw,
                               __nv_bfloat16* __restrict__ ZcH, __nv_bfloat16* __restrict__ ZcL,
                               int n4)
{
    int i = blockIdx.x*blockDim.x+threadIdx.x;
    if (i >= n4) return;
    int c4 = i & 63;
    float4 acc = make_float4(0.f,0.f,0.f,0.f);
    const int zs = NPAD*(D2/4);
#pragma unroll
    for (int k=0;k<KS;k++){
        float a = __ldg(aw+k);
        float4 v  = __ldg((const float4*)Y1 + (size_t)k*zs + i);
        float4 sc = __ldg((const float4*)(scale+k*D2)+c4);
        float4 sh = __ldg((const float4*)(shift+k*D2)+c4);
        acc.x += a*fmaxf(fmaf(v.x,sc.x,sh.x),0.f);
        acc.y += a*fmaxf(fmaf(v.y,sc.y,sh.y),0.f);
        acc.z += a*fmaxf(fmaf(v.z,sc.z,sh.z),0.f);
        acc.w += a*fmaxf(fmaf(v.w,sc.w,sh.w),0.f);
    }
    uint2 hp, lp;
    split4(acc, hp, lp);
    ((uint2*)ZcH)[i] = hp;
    ((uint2*)ZcL)[i] = lp;
}

__global__ void colstats_kernel(const float* __restrict__ X, int M, int C, size_t zstride,
                                float* __restrict__ s, float* __restrict__ q)
{
    int z = blockIdx.y;
    X += (size_t)z*zstride; s += (size_t)z*C; q += (size_t)z*C;
    int c = threadIdx.x;
    float ps=0.f, pq=0.f;
    for (int r=blockIdx.x; r<M; r+=gridDim.x){
        float v = X[(size_t)r*C+c];
        ps += v; pq += v*v;
    }
    atomicAdd(&s[c],ps); atomicAdd(&q[c],pq);
}

__global__ void finalize_kernel(const float* __restrict__ s, const float* __restrict__ q,
                                const float* __restrict__ g, const float* __restrict__ b,
                                float* __restrict__ scale, float* __restrict__ shift,
                                float invN, int C)
{
    int k = blockIdx.x, c = threadIdx.x;
    float mu = s[k*C+c]*invN;
    float var = q[k*C+c]*invN - mu*mu;
    float rstd = rsqrtf(var+1e-5f);
    float sc = rstd*g[c];
    scale[k*C+c] = sc;
    shift[k*C+c] = b[c]-mu*sc;
}

__global__ void bnrelu_kernel(const float* __restrict__ X, const float* __restrict__ scale,
                              const float* __restrict__ shift, float* __restrict__ Out, int n4)
{
    int i = blockIdx.x*blockDim.x+threadIdx.x;
    if (i >= n4) return;
    int c4 = i & 31;
    float4 v  = ((const float4*)X)[i];
    float4 sc = ((const float4*)scale)[c4];
    float4 sh = ((const float4*)shift)[c4];
    v.x=fmaxf(fmaf(v.x,sc.x,sh.x),0.f);
    v.y=fmaxf(fmaf(v.y,sc.y,sh.y),0.f);
    v.z=fmaxf(fmaf(v.z,sc.z,sh.z),0.f);
    v.w=fmaxf(fmaf(v.w,sc.w,sh.w),0.f);
    ((float4*)Out)[i] = v;
}

// ---------------------------------------------------------------------------
extern "C" void kernel_launch(void* const* d_in, const int* in_sizes, int n_in,
                              void* d_out, int out_size)
{
    const int*   x     = (const int*)  d_in[0];
    const int*   ke    = (const int*)  d_in[1];
    const float* emb   = (const float*)d_in[2];
    const float* W1    = (const float*)d_in[3];
    const float* b1    = (const float*)d_in[4];
    const float* g1    = (const float*)d_in[5];
    const float* be1   = (const float*)d_in[6];
    const float* W2    = (const float*)d_in[7];
    const float* b2    = (const float*)d_in[8];
    const float* eps   = (const float*)d_in[9];
    const float* alpha = (const float*)d_in[10];
    const float* bn_g  = (const float*)d_in[11];
    const float* bn_b  = (const float*)d_in[12];

    const int N = in_sizes[0]/NFEAT;
    const int E = in_sizes[1]/(KS*2);
    const int n4  = N*(D/4);
    const int n4b = N*(D2/4);
    const int nTilesM = (N+BM-1)/BM;

    float *p_hW,*p_y1,*p_hacc,*p_sum,*p_sq,*p_scale,*p_shift,*p_scaleD,*p_shiftD,*p_aw,*p_zero;
    __nv_bfloat16 *p_hH,*p_hL,*p_zcH,*p_zcL,*p_w1h,*p_w1l,*p_w2h,*p_w2l;
    int *p_deg,*p_dcur,*p_rowptr,*p_csrc;
    cudaGetSymbolAddress((void**)&p_hW,g_hW);
    cudaGetSymbolAddress((void**)&p_y1,g_y1);
    cudaGetSymbolAddress((void**)&p_hacc,g_hacc);
    cudaGetSymbolAddress((void**)&p_hH,g_hH);
    cudaGetSymbolAddress((void**)&p_hL,g_hL);
    cudaGetSymbolAddress((void**)&p_zcH,g_zcH);
    cudaGetSymbolAddress((void**)&p_zcL,g_zcL);
    cudaGetSymbolAddress((void**)&p_sum,g_sum);
    cudaGetSymbolAddress((void**)&p_sq,g_sq);
    cudaGetSymbolAddress((void**)&p_scale,g_scale);
    cudaGetSymbolAddress((void**)&p_shift,g_shift);
    cudaGetSymbolAddress((void**)&p_scaleD,g_scaleD);
    cudaGetSymbolAddress((void**)&p_shiftD,g_shiftD);
    cudaGetSymbolAddress((void**)&p_aw,g_aw);
    cudaGetSymbolAddress((void**)&p_zero,g_zero);
    cudaGetSymbolAddress((void**)&p_w1h,g_W1h);
    cudaGetSymbolAddress((void**)&p_w1l,g_W1l);
    cudaGetSymbolAddress((void**)&p_w2h,g_W2h);
    cudaGetSymbolAddress((void**)&p_w2l,g_W2l);
    cudaGetSymbolAddress((void**)&p_deg,g_deg);
    cudaGetSymbolAddress((void**)&p_dcur,g_dcur);
    cudaGetSymbolAddress((void**)&p_rowptr,g_rowptr);
    cudaGetSymbolAddress((void**)&p_csrc,g_csrc);

    cudaFuncSetAttribute(bgemm_kernel<D,  D2>,
                         cudaFuncAttributeMaxDynamicSharedMemorySize, SMEM_BYTES);
    cudaFuncSetAttribute(bgemm_kernel<D2, D >,
                         cudaFuncAttributeMaxDynamicSharedMemorySize, SMEM_BYTES);

    const float invN = 1.0f/(float)N;

    {
        int tot = 2*LAY*D*D2;
        wsplit_kernel<<<(tot+255)/256, 256>>>(W1, W2, p_w1h, p_w1l, p_w2h, p_w2l);
    }
    // CSR build (once; edge sets constant across layers)
    cudaMemsetAsync(p_deg, 0, (size_t)KS*N*sizeof(int));
    hist_kernel<<<(KS*E+255)/256, 256>>>(ke, p_deg, E, N);
    scan_kernel<<<KS, 1024>>>(p_deg, p_rowptr, p_dcur, N, E);
    fill_kernel<<<(KS*E+255)/256, 256>>>(ke, p_dcur, p_csrc, E, N);

    embed_split_kernel<<<(N*32+255)/256, 256>>>(x, emb, p_hH, p_hL, N);

    for (int l = 0; l < LAY; l++){
        softmax3_kernel<<<1,1>>>(alpha+l*KS, p_aw);

        if (l > 0)
            bnrelu_split_kernel<<<(n4+255)/256, 256>>>(p_hacc, p_scaleD, p_shiftD, p_hH, p_hL, n4);

        // hW = h @ W1  (no bias; ONE gemm1 — W1 commutes past the aggregation)
        bgemm_kernel<D, D2><<<dim3(nTilesM, 2), 256, SMEM_BYTES>>>(
            p_hH, p_hL, p_w1h+(size_t)l*D*D2, p_w1l+(size_t)l*D*D2, p_zero, p_hW, N);

        // y1_k = (1+eps)*hW + gather-sum(hW) + b1   (3 relations, 256-dim)
        aggregate256_kernel<<<dim3((N*32+255)/256, KS), 256>>>(
            p_hW, p_rowptr, p_csrc, eps+l, b1+l*D2, p_y1, N, E);

        cudaMemsetAsync(p_sum, 0, KS*D2*sizeof(float));
        cudaMemsetAsync(p_sq,  0, KS*D2*sizeof(float));
        colstats_kernel<<<dim3(1024,KS), D2>>>(p_y1, N, D2, (size_t)NPAD*D2, p_sum, p_sq);
        finalize_kernel<<<KS, D2>>>(p_sum, p_sq, g1+l*D2, be1+l*D2, p_scale, p_shift, invN, D2);

        combine_kernel<<<(n4b+255)/256, 256>>>(p_y1, p_scale, p_shift, p_aw, p_zcH, p_zcL, n4b);

        bgemm_kernel<D2, D><<<dim3(nTilesM, 1), 256, SMEM_BYTES>>>(
            p_zcH, p_zcL, p_w2h+(size_t)l*D2*D, p_w2l+(size_t)l*D2*D, b2+l*D, p_hacc, N);

        cudaMemsetAsync(p_sum, 0, D*sizeof(float));
        cudaMemsetAsync(p_sq,  0, D*sizeof(float));
        colstats_kernel<<<dim3(2048,1), D>>>(p_hacc, N, D, 0, p_sum, p_sq);
        finalize_kernel<<<1, D>>>(p_sum, p_sq, bn_g+l*D, bn_b+l*D, p_scaleD, p_shiftD, invN, D);

        if (l == LAY-1)
            bnrelu_kernel<<<(n4+255)/256, 256>>>(p_hacc, p_scaleD, p_shiftD, (float*)d_out, n4);
    }
}

// round 13
// speedup vs baseline: 1.2210x; 1.1521x over previous
#include <cuda_runtime.h>
#include <cuda_bf16.h>
#include <cstdint>

namespace {
constexpr int D=128, D2=256, NFEAT=9, VOC=100, KS=3, LAY=3, NPAD=100096;
constexpr int EMAX=600000;
constexpr int BM=128, BN=128, BK=32;
constexpr int OFF_AH=0, OFF_AL=20480, OFF_BH=40960, OFF_BL=58368;
constexpr int SMEM_BYTES=75776;
}

__device__ float g_hW  [NPAD * D2];                 // h @ W1 (no bias)
__device__ float g_y1  [KS * NPAD * D2];
__device__ float g_hacc[NPAD * D];
__device__ __align__(16) __nv_bfloat16 g_hH[NPAD * D];
__device__ __align__(16) __nv_bfloat16 g_hL[NPAD * D];
__device__ __align__(16) __nv_bfloat16 g_zcH[NPAD * D2];
__device__ __align__(16) __nv_bfloat16 g_zcL[NPAD * D2];
__device__ float g_sum  [KS * D2];
__device__ float g_sq   [KS * D2];
__device__ float g_scale[KS * D2];
__device__ float g_shift[KS * D2];
__device__ float g_scaleD[D];
__device__ float g_shiftD[D];
__device__ float g_aw   [KS];
__device__ float g_zero [D2];
__device__ __align__(16) __nv_bfloat16 g_W1h[LAY * D * D2];
__device__ __align__(16) __nv_bfloat16 g_W1l[LAY * D * D2];
__device__ __align__(16) __nv_bfloat16 g_W2h[LAY * D2 * D];
__device__ __align__(16) __nv_bfloat16 g_W2l[LAY * D2 * D];
// CSR scratch (built once per launch)
__device__ int g_deg   [KS * NPAD];
__device__ int g_dcur  [KS * NPAD];
__device__ int g_rowptr[KS * (NPAD + 1)];
__device__ int g_csrc  [KS * EMAX];

// ---------------- PTX helpers ----------------
__device__ __forceinline__ uint32_t smem_u32(const void* p){return (uint32_t)__cvta_generic_to_shared(p);}
__device__ __forceinline__ void ldsm_x4(uint32_t r[4], uint32_t a){
    asm volatile("ldmatrix.sync.aligned.m8n8.x4.shared.b16 {%0,%1,%2,%3},[%4];"
                 :"=r"(r[0]),"=r"(r[1]),"=r"(r[2]),"=r"(r[3]):"r"(a));
}
__device__ __forceinline__ void ldsm_x4t(uint32_t r[4], uint32_t a){
    asm volatile("ldmatrix.sync.aligned.m8n8.x4.trans.shared.b16 {%0,%1,%2,%3},[%4];"
                 :"=r"(r[0]),"=r"(r[1]),"=r"(r[2]),"=r"(r[3]):"r"(a));
}
__device__ __forceinline__ void mma16816(float c[4], const uint32_t a[4], const uint32_t* b){
    asm volatile("mma.sync.aligned.m16n8k16.row.col.f32.bf16.bf16.f32 "
                 "{%0,%1,%2,%3},{%4,%5,%6,%7},{%8,%9},{%0,%1,%2,%3};"
                 :"+f"(c[0]),"+f"(c[1]),"+f"(c[2]),"+f"(c[3])
                 :"r"(a[0]),"r"(a[1]),"r"(a[2]),"r"(a[3]),"r"(b[0]),"r"(b[1]));
}
__device__ __forceinline__ void cp16(void* d, const void* s){
    asm volatile("cp.async.cg.shared.global [%0],[%1],16;"::"r"(smem_u32(d)),"l"(s):"memory");
}
__device__ __forceinline__ uint32_t bf2(__nv_bfloat16 a, __nv_bfloat16 b){
    __nv_bfloat162 t; t.x=a; t.y=b; return *reinterpret_cast<uint32_t*>(&t);
}
__device__ __forceinline__ void split4(float4 v, uint2& hp, uint2& lp){
    __nv_bfloat16 h0=__float2bfloat16(v.x), h1=__float2bfloat16(v.y);
    __nv_bfloat16 h2=__float2bfloat16(v.z), h3=__float2bfloat16(v.w);
    hp = make_uint2(bf2(h0,h1), bf2(h2,h3));
    lp = make_uint2(
        bf2(__float2bfloat16(v.x-__bfloat162float(h0)), __float2bfloat16(v.y-__bfloat162float(h1))),
        bf2(__float2bfloat16(v.z-__bfloat162float(h2)), __float2bfloat16(v.w-__bfloat162float(h3))));
}

// ---------------- small kernels ----------------
__global__ void embed_split_kernel(const int* __restrict__ x, const float* __restrict__ emb,
                                   __nv_bfloat16* __restrict__ hH, __nv_bfloat16* __restrict__ hL,
                                   int N)
{
    int gt = blockIdx.x*blockDim.x+threadIdx.x;
    int node = gt>>5, lane = gt&31;
    if (node >= N) return;
    float4 acc = make_float4(0.f,0.f,0.f,0.f);
#pragma unroll
    for (int f=0; f<NFEAT; f++){
        int idx = x[node*NFEAT+f];
        float4 v = ((const float4*)(emb + ((size_t)f*VOC+idx)*D))[lane];
        acc.x+=v.x; acc.y+=v.y; acc.z+=v.z; acc.w+=v.w;
    }
    uint2 hp, lp;
    split4(acc, hp, lp);
    *(uint2*)(hH + (size_t)node*D + lane*4) = hp;
    *(uint2*)(hL + (size_t)node*D + lane*4) = lp;
}

__global__ void bnrelu_split_kernel(const float* __restrict__ X,
                                    const float* __restrict__ scale, const float* __restrict__ shift,
                                    __nv_bfloat16* __restrict__ hH, __nv_bfloat16* __restrict__ hL,
                                    int n4)
{
    int i = blockIdx.x*blockDim.x+threadIdx.x;
    if (i >= n4) return;
    int c4 = i & 31;
    float4 v  = ((const float4*)X)[i];
    float4 sc = ((const float4*)scale)[c4];
    float4 sh = ((const float4*)shift)[c4];
    v.x=fmaxf(fmaf(v.x,sc.x,sh.x),0.f);
    v.y=fmaxf(fmaf(v.y,sc.y,sh.y),0.f);
    v.z=fmaxf(fmaf(v.z,sc.z,sh.z),0.f);
    v.w=fmaxf(fmaf(v.w,sc.w,sh.w),0.f);
    uint2 hp, lp;
    split4(v, hp, lp);
    ((uint2*)hH)[i] = hp;
    ((uint2*)hL)[i] = lp;
}

__global__ void softmax3_kernel(const float* __restrict__ alpha, float* __restrict__ a)
{
    float a0=alpha[0],a1=alpha[1],a2=alpha[2];
    float m=fmaxf(a0,fmaxf(a1,a2));
    float e0=expf(a0-m),e1=expf(a1-m),e2=expf(a2-m);
    float inv=1.f/(e0+e1+e2);
    a[0]=e0*inv; a[1]=e1*inv; a[2]=e2*inv;
}

__global__ void wsplit_kernel(const float* __restrict__ W1, const float* __restrict__ W2,
                              __nv_bfloat16* __restrict__ w1h, __nv_bfloat16* __restrict__ w1l,
                              __nv_bfloat16* __restrict__ w2h, __nv_bfloat16* __restrict__ w2l)
{
    int i = blockIdx.x*blockDim.x+threadIdx.x;
    const int tot = LAY*D*D2;
    if (i < tot){
        float v = W1[i];
        __nv_bfloat16 h = __float2bfloat16(v);
        w1h[i] = h;
        w1l[i] = __float2bfloat16(v-__bfloat162float(h));
    } else if (i < 2*tot){
        int j = i-tot;
        float v = W2[j];
        __nv_bfloat16 h = __float2bfloat16(v);
        w2h[j] = h;
        w2l[j] = __float2bfloat16(v-__bfloat162float(h));
    }
}

// ---------------- CSR build ----------------
__global__ void hist_kernel(const int* __restrict__ ke, int* __restrict__ deg, int E, int N)
{
    int i = blockIdx.x*blockDim.x+threadIdx.x;
    if (i >= KS*E) return;
    int k = i/E, e = i - k*E;
    int d = ke[(size_t)(k*2+1)*E + e];
    atomicAdd(&deg[k*N + d], 1);
}

__global__ void scan_kernel(const int* __restrict__ deg, int* __restrict__ rowptr,
                            int* __restrict__ dcur, int N, int E)
{
    const int T = 1024;
    int k = blockIdx.x, t = threadIdx.x;
    int chunk = (N + T - 1)/T;
    int lo = t*chunk, hi = min(lo+chunk, N);
    int s = 0;
    for (int i=lo; i<hi; i++) s += deg[k*N+i];
    __shared__ int ps[T];
    ps[t] = s;
    __syncthreads();
    for (int off=1; off<T; off<<=1){
        int v = (t>=off) ? ps[t-off] : 0;
        __syncthreads();
        ps[t] += v;
        __syncthreads();
    }
    int run = (t>0) ? ps[t-1] : 0;
    for (int i=lo; i<hi; i++){
        rowptr[k*(N+1)+i] = run;
        dcur[k*N+i] = run;
        run += deg[k*N+i];
    }
    if (t == 0) rowptr[k*(N+1)+N] = E;
}

__global__ void fill_kernel(const int* __restrict__ ke, int* __restrict__ dcur,
                            int* __restrict__ csrc, int E, int N)
{
    int i = blockIdx.x*blockDim.x+threadIdx.x;
    if (i >= KS*E) return;
    int k = i/E, e = i - k*E;
    int s = ke[(size_t)(k*2)*E + e];
    int d = ke[(size_t)(k*2+1)*E + e];
    int pos = atomicAdd(&dcur[k*N + d], 1);
    csrc[k*E + pos] = s;
}

// ---------------------------------------------------------------------------
// aggregate256 + FUSED per-k column stats.
// grid (ceil(N/64), KS); 8 warps/block, each warp does 8 consecutive nodes.
// y1_k[n] = (1+eps)*hW[n] + sum_{src} hW[src] + b1.
// Each lane owns columns [lane*4..+3] and [128+lane*4..+3]; accumulates
// sum/sumsq in registers across its nodes, block-reduces via smem, then
// 2 global atomics per thread.
// ---------------------------------------------------------------------------
__global__ __launch_bounds__(256) void aggregate256_stats_kernel(
    const float* __restrict__ hW,
    const int* __restrict__ rowptr, const int* __restrict__ csrc,
    const float* __restrict__ epsp, const float* __restrict__ b1,
    float* __restrict__ Y1, float* __restrict__ gsum, float* __restrict__ gsq,
    int N, int E)
{
    __shared__ float ssum[D2], ssq[D2];
    const int tid = threadIdx.x, wid = tid>>5, lane = tid&31;
    const int k = blockIdx.y;
    const int nodeBase = blockIdx.x*64 + wid*8;
    if (tid < D2){ ssum[tid]=0.f; ssq[tid]=0.f; }
    __syncthreads();

    const float se = 1.0f + epsp[0];
    const float4 bb0 = __ldg((const float4*)b1 + lane);
    const float4 bb1 = __ldg((const float4*)b1 + lane + 32);
    const int* cs = csrc + (size_t)k*E;
    const int* rp = rowptr + k*(N+1);

    float4 s0=make_float4(0,0,0,0), q0=make_float4(0,0,0,0);
    float4 s1=make_float4(0,0,0,0), q1=make_float4(0,0,0,0);

    for (int i = 0; i < 8; i++){
        int gw = nodeBase + i;
        if (gw >= N) break;
        const float4* row = (const float4*)(hW + (size_t)gw*D2);
        float4 c0 = __ldg(row + lane);
        float4 c1 = __ldg(row + lane + 32);
        c0.x*=se; c0.y*=se; c0.z*=se; c0.w*=se;
        c1.x*=se; c1.y*=se; c1.z*=se; c1.w*=se;

        int lo = __ldg(rp + gw), hi = __ldg(rp + gw + 1);
        int j = lo;
        for (; j + 2 <= hi; j += 2){
            int a = __ldg(cs+j), b = __ldg(cs+j+1);
            const float4* ra = (const float4*)(hW + (size_t)a*D2);
            const float4* rb = (const float4*)(hW + (size_t)b*D2);
            float4 a0=__ldg(ra+lane), a1=__ldg(ra+lane+32);
            float4 b0=__ldg(rb+lane), b1v=__ldg(rb+lane+32);
            c0.x += a0.x+b0.x; c0.y += a0.y+b0.y; c0.z += a0.z+b0.z; c0.w += a0.w+b0.w;
            c1.x += a1.x+b1v.x; c1.y += a1.y+b1v.y; c1.z += a1.z+b1v.z; c1.w += a1.w+b1v.w;
        }
        for (; j < hi; j++){
            int a = __ldg(cs+j);
            const float4* ra = (const float4*)(hW + (size_t)a*D2);
            float4 a0=__ldg(ra+lane), a1=__ldg(ra+lane+32);
            c0.x+=a0.x; c0.y+=a0.y; c0.z+=a0.z; c0.w+=a0.w;
            c1.x+=a1.x; c1.y+=a1.y; c1.z+=a1.z; c1.w+=a1.w;
        }
        c0.x+=bb0.x; c0.y+=bb0.y; c0.z+=bb0.z; c0.w+=bb0.w;
        c1.x+=bb1.x; c1.y+=bb1.y; c1.z+=bb1.z; c1.w+=bb1.w;

        float4* out = (float4*)(Y1 + (size_t)k*NPAD*D2 + (size_t)gw*D2);
        out[lane] = c0;
        out[lane+32] = c1;

        s0.x+=c0.x; s0.y+=c0.y; s0.z+=c0.z; s0.w+=c0.w;
        q0.x+=c0.x*c0.x; q0.y+=c0.y*c0.y; q0.z+=c0.z*c0.z; q0.w+=c0.w*c0.w;
        s1.x+=c1.x; s1.y+=c1.y; s1.z+=c1.z; s1.w+=c1.w;
        q1.x+=c1.x*c1.x; q1.y+=c1.y*c1.y; q1.z+=c1.z*c1.z; q1.w+=c1.w*c1.w;
    }

    // block-level reduction (8 warps share the same column ownership)
    int c0i = lane*4, c1i = 128 + lane*4;
    atomicAdd(&ssum[c0i+0], s0.x); atomicAdd(&ssum[c0i+1], s0.y);
    atomicAdd(&ssum[c0i+2], s0.z); atomicAdd(&ssum[c0i+3], s0.w);
    atomicAdd(&ssq [c0i+0], q0.x); atomicAdd(&ssq [c0i+1], q0.y);
    atomicAdd(&ssq [c0i+2], q0.z); atomicAdd(&ssq [c0i+3], q0.w);
    atomicAdd(&ssum[c1i+0], s1.x); atomicAdd(&ssum[c1i+1], s1.y);
    atomicAdd(&ssum[c1i+2], s1.z); atomicAdd(&ssum[c1i+3], s1.w);
    atomicAdd(&ssq [c1i+0], q1.x); atomicAdd(&ssq [c1i+1], q1.y);
    atomicAdd(&ssq [c1i+2], q1.z); atomicAdd(&ssq [c1i+3], q1.w);
    __syncthreads();
    if (tid < D2){
        atomicAdd(&gsum[k*D2 + tid], ssum[tid]);
        atomicAdd(&gsq [k*D2 + tid], ssq [tid]);
    }
}

// ---------------------------------------------------------------------------
// Pure-bf16 pipelined HMMA GEMM (2 planes, 3 combos).
// ---------------------------------------------------------------------------
template <int KTOT, int NTOT>
__global__ __launch_bounds__(256, 2) void bgemm_kernel(
    const __nv_bfloat16* __restrict__ Ahp, const __nv_bfloat16* __restrict__ Alp,
    const __nv_bfloat16* __restrict__ Bhp, const __nv_bfloat16* __restrict__ Blp,
    const float* __restrict__ bias,
    float* __restrict__ C, int M)
{
    extern __shared__ __align__(16) char dynsm[];
    __nv_bfloat16* sAh = (__nv_bfloat16*)(dynsm+OFF_AH);
    __nv_bfloat16* sAl = (__nv_bfloat16*)(dynsm+OFF_AL);
    __nv_bfloat16* sBh = (__nv_bfloat16*)(dynsm+OFF_BH);
    __nv_bfloat16* sBl = (__nv_bfloat16*)(dynsm+OFF_BL);

    const int tid=threadIdx.x, wid=tid>>5, lane=tid&31;
    const int wm=wid>>1, wn=wid&1;
    const int rowBase=blockIdx.x*BM, colBase=blockIdx.y*BN;

    const int ar=tid>>1, ahh=tid&1;
    const int br=tid>>4, bcv=tid&15;

    auto issue_tile=[&](int t,int s){
        const int kk=t*BK;
        __nv_bfloat16* ahDst=sAh+s*(128*40);
        __nv_bfloat16* alDst=sAl+s*(128*40);
#pragma unroll
        for (int j=0;j<2;j++){
            int col = ahh*16 + j*8;
            cp16(ahDst+ar*40+col, Ahp+(size_t)(rowBase+ar)*KTOT+kk+col);
            cp16(alDst+ar*40+col, Alp+(size_t)(rowBase+ar)*KTOT+kk+col);
        }
        __nv_bfloat16* bhDst=sBh+s*(32*136);
        __nv_bfloat16* blDst=sBl+s*(32*136);
#pragma unroll
        for (int p=0;p<2;p++){
            int r=br+p*16;
            cp16(bhDst+r*136+bcv*8, Bhp+(size_t)(kk+r)*NTOT+colBase+bcv*8);
            cp16(blDst+r*136+bcv*8, Blp+(size_t)(kk+r)*NTOT+colBase+bcv*8);
        }
    };

    issue_tile(0,0);
    asm volatile("cp.async.commit_group;":::"memory");

    float acc[2][8][4];
#pragma unroll
    for (int m=0;m<2;m++)
#pragma unroll
        for (int n=0;n<8;n++)
#pragma unroll
            for (int q=0;q<4;q++) acc[m][n][q]=0.f;

    const int ktiles=KTOT/BK;
    for (int t=0;t<ktiles;t++){
        const int s=t&1;
        asm volatile("cp.async.wait_group 0;":::"memory");
        __syncthreads();
        if (t+1<ktiles){ issue_tile(t+1,s^1); asm volatile("cp.async.commit_group;":::"memory"); }

        const __nv_bfloat16 *ah_s=sAh+s*(128*40), *al_s=sAl+s*(128*40);
        const __nv_bfloat16 *bh_s=sBh+s*(32*136), *bl_s=sBl+s*(32*136);
#pragma unroll
        for (int kb=0;kb<BK/16;kb++){
            uint32_t ah[2][4], al[2][4], bf[8][2];
#pragma unroll
            for (int m=0;m<2;m++){
                int row=wm*32+m*16+(lane&15), col=kb*16+(lane>>4)*8;
                ldsm_x4(ah[m], smem_u32(ah_s+row*40+col));
                ldsm_x4(al[m], smem_u32(al_s+row*40+col));
            }
#pragma unroll
            for (int nb=0;nb<4;nb++){
                int row=kb*16+(lane&15), col=wn*64+nb*16+(lane>>4)*8;
                uint32_t tr[4];
                ldsm_x4t(tr, smem_u32(bh_s+row*136+col));
                bf[nb*2][0]=tr[0]; bf[nb*2][1]=tr[1];
                bf[nb*2+1][0]=tr[2]; bf[nb*2+1][1]=tr[3];
            }
#pragma unroll
            for (int m=0;m<2;m++)
#pragma unroll
                for (int n=0;n<8;n++) mma16816(acc[m][n],ah[m],bf[n]);
#pragma unroll
            for (int m=0;m<2;m++)
#pragma unroll
                for (int n=0;n<8;n++) mma16816(acc[m][n],al[m],bf[n]);
#pragma unroll
            for (int nb=0;nb<4;nb++){
                int row=kb*16+(lane&15), col=wn*64+nb*16+(lane>>4)*8;
                uint32_t tr[4];
                ldsm_x4t(tr, smem_u32(bl_s+row*136+col));
                bf[nb*2][0]=tr[0]; bf[nb*2][1]=tr[1];
                bf[nb*2+1][0]=tr[2]; bf[nb*2+1][1]=tr[3];
            }
#pragma unroll
            for (int m=0;m<2;m++)
#pragma unroll
                for (int n=0;n<8;n++) mma16816(acc[m][n],ah[m],bf[n]);
        }
    }

#pragma unroll
    for (int m=0;m<2;m++){
        int rbase=rowBase+wm*32+m*16+(lane>>2);
#pragma unroll
        for (int half=0;half<2;half++){
            int rr=rbase+half*8;
            if (rr<M){
#pragma unroll
                for (int n=0;n<8;n++){
                    int c=colBase+wn*64+n*8+(lane&3)*2;
                    float2 o;
                    o.x=acc[m][n][half*2+0]+bias[c];
                    o.y=acc[m][n][half*2+1]+bias[c+1];
                    *(float2*)(C+(size_t)rr*NTOT+c)=o;
                }
            }
        }
    }
}

// zc = sum_k aw[k] * relu( y1_k * scale_k + shift_k )  -> split bf16 planes
__global__ void combine_kernel(const float* __restrict__ Y1, const float* __restrict__ scale,
                               const float* __restrict__ shift, const float* __restrict__ aw,
                               __nv_bfloat16* __restrict__ ZcH, __nv_bfloat16* __restrict__ ZcL,
                               int n4)
{
    int i = blockIdx.x*blockDim.x+threadIdx.x;
    if (i >= n4) return;
    int c4 = i & 63;
    float4 acc = make_float4(0.f,0.f,0.f,0.f);
    const int zs = NPAD*(D2/4);
#pragma unroll
    for (int k=0;k<KS;k++){
        float a = __ldg(aw+k);
        float4 v  = __ldg((const float4*)Y1 + (size_t)k*zs + i);
        float4 sc = __ldg((const float4*)(scale+k*D2)+c4);
        float4 sh = __ldg((const float4*)(shift+k*D2)+c4);
        acc.x += a*fmaxf(fmaf(v.x,sc.x,sh.x),0.f);
        acc.y += a*fmaxf(fmaf(v.y,sc.y,sh.y),0.f);
        acc.z += a*fmaxf(fmaf(v.z,sc.z,sh.z),0.f);
        acc.w += a*fmaxf(fmaf(v.w,sc.w,sh.w),0.f);
    }
    uint2 hp, lp;
    split4(acc, hp, lp);
    ((uint2*)ZcH)[i] = hp;
    ((uint2*)ZcL)[i] = lp;
}

__global__ void colstats_kernel(const float* __restrict__ X, int M, int C,
                                float* __restrict__ s, float* __restrict__ q)
{
    int c = threadIdx.x;
    float ps=0.f, pq=0.f;
    for (int r=blockIdx.x; r<M; r+=gridDim.x){
        float v = X[(size_t)r*C+c];
        ps += v; pq += v*v;
    }
    atomicAdd(&s[c],ps); atomicAdd(&q[c],pq);
}

__global__ void finalize_kernel(const float* __restrict__ s, const float* __restrict__ q,
                                const float* __restrict__ g, const float* __restrict__ b,
                                float* __restrict__ scale, float* __restrict__ shift,
                                float invN, int C)
{
    int k = blockIdx.x, c = threadIdx.x;
    float mu = s[k*C+c]*invN;
    float var = q[k*C+c]*invN - mu*mu;
    float rstd = rsqrtf(var+1e-5f);
    float sc = rstd*g[c];
    scale[k*C+c] = sc;
    shift[k*C+c] = b[c]-mu*sc;
}

__global__ void bnrelu_kernel(const float* __restrict__ X, const float* __restrict__ scale,
                              const float* __restrict__ shift, float* __restrict__ Out, int n4)
{
    int i = blockIdx.x*blockDim.x+threadIdx.x;
    if (i >= n4) return;
    int c4 = i & 31;
    float4 v  = ((const float4*)X)[i];
    float4 sc = ((const float4*)scale)[c4];
    float4 sh = ((const float4*)shift)[c4];
    v.x=fmaxf(fmaf(v.x,sc.x,sh.x),0.f);
    v.y=fmaxf(fmaf(v.y,sc.y,sh.y),0.f);
    v.z=fmaxf(fmaf(v.z,sc.z,sh.z),0.f);
    v.w=fmaxf(fmaf(v.w,sc.w,sh.w),0.f);
    ((float4*)Out)[i] = v;
}

// ---------------------------------------------------------------------------
extern "C" void kernel_launch(void* const* d_in, const int* in_sizes, int n_in,
                              void* d_out, int out_size)
{
    const int*   x     = (const int*)  d_in[0];
    const int*   ke    = (const int*)  d_in[1];
    const float* emb   = (const float*)d_in[2];
    const float* W1    = (const float*)d_in[3];
    const float* b1    = (const float*)d_in[4];
    const float* g1    = (const float*)d_in[5];
    const float* be1   = (const float*)d_in[6];
    const float* W2    = (const float*)d_in[7];
    const float* b2    = (const float*)d_in[8];
    const float* eps   = (const float*)d_in[9];
    const float* alpha = (const float*)d_in[10];
    const float* bn_g  = (const float*)d_in[11];
    const float* bn_b  = (const float*)d_in[12];

    const int N = in_sizes[0]/NFEAT;
    const int E = in_sizes[1]/(KS*2);
    const int n4  = N*(D/4);
    const int n4b = N*(D2/4);
    const int nTilesM = (N+BM-1)/BM;

    float *p_hW,*p_y1,*p_hacc,*p_sum,*p_sq,*p_scale,*p_shift,*p_scaleD,*p_shiftD,*p_aw,*p_zero;
    __nv_bfloat16 *p_hH,*p_hL,*p_zcH,*p_zcL,*p_w1h,*p_w1l,*p_w2h,*p_w2l;
    int *p_deg,*p_dcur,*p_rowptr,*p_csrc;
    cudaGetSymbolAddress((void**)&p_hW,g_hW);
    cudaGetSymbolAddress((void**)&p_y1,g_y1);
    cudaGetSymbolAddress((void**)&p_hacc,g_hacc);
    cudaGetSymbolAddress((void**)&p_hH,g_hH);
    cudaGetSymbolAddress((void**)&p_hL,g_hL);
    cudaGetSymbolAddress((void**)&p_zcH,g_zcH);
    cudaGetSymbolAddress((void**)&p_zcL,g_zcL);
    cudaGetSymbolAddress((void**)&p_sum,g_sum);
    cudaGetSymbolAddress((void**)&p_sq,g_sq);
    cudaGetSymbolAddress((void**)&p_scale,g_scale);
    cudaGetSymbolAddress((void**)&p_shift,g_shift);
    cudaGetSymbolAddress((void**)&p_scaleD,g_scaleD);
    cudaGetSymbolAddress((void**)&p_shiftD,g_shiftD);
    cudaGetSymbolAddress((void**)&p_aw,g_aw);
    cudaGetSymbolAddress((void**)&p_zero,g_zero);
    cudaGetSymbolAddress((void**)&p_w1h,g_W1h);
    cudaGetSymbolAddress((void**)&p_w1l,g_W1l);
    cudaGetSymbolAddress((void**)&p_w2h,g_W2h);
    cudaGetSymbolAddress((void**)&p_w2l,g_W2l);
    cudaGetSymbolAddress((void**)&p_deg,g_deg);
    cudaGetSymbolAddress((void**)&p_dcur,g_dcur);
    cudaGetSymbolAddress((void**)&p_rowptr,g_rowptr);
    cudaGetSymbolAddress((void**)&p_csrc,g_csrc);

    cudaFuncSetAttribute(bgemm_kernel<D,  D2>,
                         cudaFuncAttributeMaxDynamicSharedMemorySize, SMEM_BYTES);
    cudaFuncSetAttribute(bgemm_kernel<D2, D >,
                         cudaFuncAttributeMaxDynamicSharedMemorySize, SMEM_BYTES);

    const float invN = 1.0f/(float)N;

    {
        int tot = 2*LAY*D*D2;
        wsplit_kernel<<<(tot+255)/256, 256>>>(W1, W2, p_w1h, p_w1l, p_w2h, p_w2l);
    }
    cudaMemsetAsync(p_deg, 0, (size_t)KS*N*sizeof(int));
    hist_kernel<<<(KS*E+255)/256, 256>>>(ke, p_deg, E, N);
    scan_kernel<<<KS, 1024>>>(p_deg, p_rowptr, p_dcur, N, E);
    fill_kernel<<<(KS*E+255)/256, 256>>>(ke, p_dcur, p_csrc, E, N);

    embed_split_kernel<<<(N*32+255)/256, 256>>>(x, emb, p_hH, p_hL, N);

    for (int l = 0; l < LAY; l++){
        softmax3_kernel<<<1,1>>>(alpha+l*KS, p_aw);

        if (l > 0)
            bnrelu_split_kernel<<<(n4+255)/256, 256>>>(p_hacc, p_scaleD, p_shiftD, p_hH, p_hL, n4);

        // hW = h @ W1  (one gemm1; W1 commutes past the aggregation)
        bgemm_kernel<D, D2><<<dim3(nTilesM, 2), 256, SMEM_BYTES>>>(
            p_hH, p_hL, p_w1h+(size_t)l*D*D2, p_w1l+(size_t)l*D*D2, p_zero, p_hW, N);

        // y1_k = (1+eps)hW + gather + b1, with FUSED per-k column stats
        cudaMemsetAsync(p_sum, 0, KS*D2*sizeof(float));
        cudaMemsetAsync(p_sq,  0, KS*D2*sizeof(float));
        aggregate256_stats_kernel<<<dim3((N+63)/64, KS), 256>>>(
            p_hW, p_rowptr, p_csrc, eps+l, b1+l*D2, p_y1, p_sum, p_sq, N, E);
        finalize_kernel<<<KS, D2>>>(p_sum, p_sq, g1+l*D2, be1+l*D2, p_scale, p_shift, invN, D2);

        combine_kernel<<<(n4b+255)/256, 256>>>(p_y1, p_scale, p_shift, p_aw, p_zcH, p_zcL, n4b);

        bgemm_kernel<D2, D><<<dim3(nTilesM, 1), 256, SMEM_BYTES>>>(
            p_zcH, p_zcL, p_w2h+(size_t)l*D2*D, p_w2l+(size_t)l*D2*D, b2+l*D, p_hacc, N);

        cudaMemsetAsync(p_sum, 0, D*sizeof(float));
        cudaMemsetAsync(p_sq,  0, D*sizeof(float));
        colstats_kernel<<<2048, D>>>(p_hacc, N, D, p_sum, p_sq);
        finalize_kernel<<<1, D>>>(p_sum, p_sq, bn_g+l*D, bn_b+l*D, p_scaleD, p_shiftD, invN, D);

        if (l == LAY-1)
            bnrelu_kernel<<<(n4+255)/256, 256>>>(p_hacc, p_scaleD, p_shiftD, (float*)d_out, n4);
    }
}

// round 15
// speedup vs baseline: 1.2576x; 1.0300x over previous
#include <cuda_runtime.h>
#include <cuda_bf16.h>
#include <cstdint>

namespace {
constexpr int D=128, D2=256, NFEAT=9, VOC=100, KS=3, LAY=3, NPAD=100096;
constexpr int EMAX=600000;
constexpr int BM=128, BN=128, BK=32;
// plain bf16 gemm1 smem
constexpr int OFF_AH=0, OFF_AL=20480, OFF_BH=40960, OFF_BL=58368;
constexpr int SMEM_BYTES=75776;
// fused gemm2 smem (bytes)
constexpr int F_RAW=0;                         // 2 st x 3 k x 128x32 f32 = 98304
constexpr int F_AH =98304;                     // 2 st x 128x40 bf16    = 20480
constexpr int F_AL =118784;
constexpr int F_BH =139264;                    // 2 st x 32x136 bf16    = 17408
constexpr int F_BL =156672;
constexpr int F_SC =174080;                    // 3x256 f32 = 3072
constexpr int F_SH =177152;
constexpr int F_SMEM=180224;
}

__device__ float g_hW  [NPAD * D2];
__device__ float g_y1  [KS * NPAD * D2];
__device__ float g_hacc[NPAD * D];
__device__ __align__(16) __nv_bfloat16 g_hH[NPAD * D];
__device__ __align__(16) __nv_bfloat16 g_hL[NPAD * D];
__device__ float g_sum  [KS * D2];
__device__ float g_sq   [KS * D2];
__device__ float g_scale[KS * D2];
__device__ float g_shift[KS * D2];
__device__ float g_scaleD[D];
__device__ float g_shiftD[D];
__device__ float g_aw   [KS];
__device__ float g_zero [D2];
__device__ __align__(16) __nv_bfloat16 g_W1h[LAY * D * D2];
__device__ __align__(16) __nv_bfloat16 g_W1l[LAY * D * D2];
__device__ __align__(16) __nv_bfloat16 g_W2h[LAY * D2 * D];
__device__ __align__(16) __nv_bfloat16 g_W2l[LAY * D2 * D];
__device__ int g_deg   [KS * NPAD];
__device__ int g_dcur  [KS * NPAD];
__device__ int g_rowptr[KS * (NPAD + 1)];
__device__ int g_csrc  [KS * EMAX];

// ---------------- PTX helpers ----------------
__device__ __forceinline__ uint32_t smem_u32(const void* p){return (uint32_t)__cvta_generic_to_shared(p);}
__device__ __forceinline__ void ldsm_x4(uint32_t r[4], uint32_t a){
    asm volatile("ldmatrix.sync.aligned.m8n8.x4.shared.b16 {%0,%1,%2,%3},[%4];"
                 :"=r"(r[0]),"=r"(r[1]),"=r"(r[2]),"=r"(r[3]):"r"(a));
}
__device__ __forceinline__ void ldsm_x4t(uint32_t r[4], uint32_t a){
    asm volatile("ldmatrix.sync.aligned.m8n8.x4.trans.shared.b16 {%0,%1,%2,%3},[%4];"
                 :"=r"(r[0]),"=r"(r[1]),"=r"(r[2]),"=r"(r[3]):"r"(a));
}
__device__ __forceinline__ void mma16816(float c[4], const uint32_t a[4], const uint32_t* b){
    asm volatile("mma.sync.aligned.m16n8k16.row.col.f32.bf16.bf16.f32 "
                 "{%0,%1,%2,%3},{%4,%5,%6,%7},{%8,%9},{%0,%1,%2,%3};"
                 :"+f"(c[0]),"+f"(c[1]),"+f"(c[2]),"+f"(c[3])
                 :"r"(a[0]),"r"(a[1]),"r"(a[2]),"r"(a[3]),"r"(b[0]),"r"(b[1]));
}
__device__ __forceinline__ void cp16(void* d, const void* s){
    asm volatile("cp.async.cg.shared.global [%0],[%1],16;"::"r"(smem_u32(d)),"l"(s):"memory");
}
__device__ __forceinline__ uint32_t bf2(__nv_bfloat16 a, __nv_bfloat16 b){
    __nv_bfloat162 t; t.x=a; t.y=b; return *reinterpret_cast<uint32_t*>(&t);
}
__device__ __forceinline__ void split4(float4 v, uint2& hp, uint2& lp){
    __nv_bfloat16 h0=__float2bfloat16(v.x), h1=__float2bfloat16(v.y);
    __nv_bfloat16 h2=__float2bfloat16(v.z), h3=__float2bfloat16(v.w);
    hp = make_uint2(bf2(h0,h1), bf2(h2,h3));
    lp = make_uint2(
        bf2(__float2bfloat16(v.x-__bfloat162float(h0)), __float2bfloat16(v.y-__bfloat162float(h1))),
        bf2(__float2bfloat16(v.z-__bfloat162float(h2)), __float2bfloat16(v.w-__bfloat162float(h3))));
}

// ---------------- small kernels ----------------
__global__ void embed_split_kernel(const int* __restrict__ x, const float* __restrict__ emb,
                                   __nv_bfloat16* __restrict__ hH, __nv_bfloat16* __restrict__ hL,
                                   int N)
{
    int gt = blockIdx.x*blockDim.x+threadIdx.x;
    int node = gt>>5, lane = gt&31;
    if (node >= N) return;
    float4 acc = make_float4(0.f,0.f,0.f,0.f);
#pragma unroll
    for (int f=0; f<NFEAT; f++){
        int idx = x[node*NFEAT+f];
        float4 v = ((const float4*)(emb + ((size_t)f*VOC+idx)*D))[lane];
        acc.x+=v.x; acc.y+=v.y; acc.z+=v.z; acc.w+=v.w;
    }
    uint2 hp, lp;
    split4(acc, hp, lp);
    *(uint2*)(hH + (size_t)node*D + lane*4) = hp;
    *(uint2*)(hL + (size_t)node*D + lane*4) = lp;
}

__global__ void bnrelu_split_kernel(const float* __restrict__ X,
                                    const float* __restrict__ scale, const float* __restrict__ shift,
                                    __nv_bfloat16* __restrict__ hH, __nv_bfloat16* __restrict__ hL,
                                    int n4)
{
    int i = blockIdx.x*blockDim.x+threadIdx.x;
    if (i >= n4) return;
    int c4 = i & 31;
    float4 v  = ((const float4*)X)[i];
    float4 sc = ((const float4*)scale)[c4];
    float4 sh = ((const float4*)shift)[c4];
    v.x=fmaxf(fmaf(v.x,sc.x,sh.x),0.f);
    v.y=fmaxf(fmaf(v.y,sc.y,sh.y),0.f);
    v.z=fmaxf(fmaf(v.z,sc.z,sh.z),0.f);
    v.w=fmaxf(fmaf(v.w,sc.w,sh.w),0.f);
    uint2 hp, lp;
    split4(v, hp, lp);
    ((uint2*)hH)[i] = hp;
    ((uint2*)hL)[i] = lp;
}

__global__ void softmax3_kernel(const float* __restrict__ alpha, float* __restrict__ a)
{
    float a0=alpha[0],a1=alpha[1],a2=alpha[2];
    float m=fmaxf(a0,fmaxf(a1,a2));
    float e0=expf(a0-m),e1=expf(a1-m),e2=expf(a2-m);
    float inv=1.f/(e0+e1+e2);
    a[0]=e0*inv; a[1]=e1*inv; a[2]=e2*inv;
}

__global__ void wsplit_kernel(const float* __restrict__ W1, const float* __restrict__ W2,
                              __nv_bfloat16* __restrict__ w1h, __nv_bfloat16* __restrict__ w1l,
                              __nv_bfloat16* __restrict__ w2h, __nv_bfloat16* __restrict__ w2l)
{
    int i = blockIdx.x*blockDim.x+threadIdx.x;
    const int tot = LAY*D*D2;
    if (i < tot){
        float v = W1[i];
        __nv_bfloat16 h = __float2bfloat16(v);
        w1h[i] = h;
        w1l[i] = __float2bfloat16(v-__bfloat162float(h));
    } else if (i < 2*tot){
        int j = i-tot;
        float v = W2[j];
        __nv_bfloat16 h = __float2bfloat16(v);
        w2h[j] = h;
        w2l[j] = __float2bfloat16(v-__bfloat162float(h));
    }
}

// ---------------- CSR build ----------------
__global__ void hist_kernel(const int* __restrict__ ke, int* __restrict__ deg, int E, int N)
{
    int i = blockIdx.x*blockDim.x+threadIdx.x;
    if (i >= KS*E) return;
    int k = i/E, e = i - k*E;
    int d = ke[(size_t)(k*2+1)*E + e];
    atomicAdd(&deg[k*N + d], 1);
}

__global__ void scan_kernel(const int* __restrict__ deg, int* __restrict__ rowptr,
                            int* __restrict__ dcur, int N, int E)
{
    const int T = 1024;
    int k = blockIdx.x, t = threadIdx.x;
    int chunk = (N + T - 1)/T;
    int lo = t*chunk, hi = min(lo+chunk, N);
    int s = 0;
    for (int i=lo; i<hi; i++) s += deg[k*N+i];
    __shared__ int ps[T];
    ps[t] = s;
    __syncthreads();
    for (int off=1; off<T; off<<=1){
        int v = (t>=off) ? ps[t-off] : 0;
        __syncthreads();
        ps[t] += v;
        __syncthreads();
    }
    int run = (t>0) ? ps[t-1] : 0;
    for (int i=lo; i<hi; i++){
        rowptr[k*(N+1)+i] = run;
        dcur[k*N+i] = run;
        run += deg[k*N+i];
    }
    if (t == 0) rowptr[k*(N+1)+N] = E;
}

__global__ void fill_kernel(const int* __restrict__ ke, int* __restrict__ dcur,
                            int* __restrict__ csrc, int E, int N)
{
    int i = blockIdx.x*blockDim.x+threadIdx.x;
    if (i >= KS*E) return;
    int k = i/E, e = i - k*E;
    int s = ke[(size_t)(k*2)*E + e];
    int d = ke[(size_t)(k*2+1)*E + e];
    int pos = atomicAdd(&dcur[k*N + d], 1);
    csrc[k*E + pos] = s;
}

// ---------------------------------------------------------------------------
// aggregate256 + fused per-k column stats (R13 win, unchanged)
// ---------------------------------------------------------------------------
__global__ __launch_bounds__(256) void aggregate256_stats_kernel(
    const float* __restrict__ hW,
    const int* __restrict__ rowptr, const int* __restrict__ csrc,
    const float* __restrict__ epsp, const float* __restrict__ b1,
    float* __restrict__ Y1, float* __restrict__ gsum, float* __restrict__ gsq,
    int N, int E)
{
    __shared__ float ssum[D2], ssq[D2];
    const int tid = threadIdx.x, wid = tid>>5, lane = tid&31;
    const int k = blockIdx.y;
    const int nodeBase = blockIdx.x*64 + wid*8;
    if (tid < D2){ ssum[tid]=0.f; ssq[tid]=0.f; }
    __syncthreads();

    const float se = 1.0f + epsp[0];
    const float4 bb0 = __ldg((const float4*)b1 + lane);
    const float4 bb1 = __ldg((const float4*)b1 + lane + 32);
    const int* cs = csrc + (size_t)k*E;
    const int* rp = rowptr + k*(N+1);

    float4 s0=make_float4(0,0,0,0), q0=make_float4(0,0,0,0);
    float4 s1=make_float4(0,0,0,0), q1=make_float4(0,0,0,0);

    for (int i = 0; i < 8; i++){
        int gw = nodeBase + i;
        if (gw >= N) break;
        const float4* row = (const float4*)(hW + (size_t)gw*D2);
        float4 c0 = __ldg(row + lane);
        float4 c1 = __ldg(row + lane + 32);
        c0.x*=se; c0.y*=se; c0.z*=se; c0.w*=se;
        c1.x*=se; c1.y*=se; c1.z*=se; c1.w*=se;

        int lo = __ldg(rp + gw), hi = __ldg(rp + gw + 1);
        int j = lo;
        for (; j + 2 <= hi; j += 2){
            int a = __ldg(cs+j), b = __ldg(cs+j+1);
            const float4* ra = (const float4*)(hW + (size_t)a*D2);
            const float4* rb = (const float4*)(hW + (size_t)b*D2);
            float4 a0=__ldg(ra+lane), a1=__ldg(ra+lane+32);
            float4 b0=__ldg(rb+lane), b1v=__ldg(rb+lane+32);
            c0.x += a0.x+b0.x; c0.y += a0.y+b0.y; c0.z += a0.z+b0.z; c0.w += a0.w+b0.w;
            c1.x += a1.x+b1v.x; c1.y += a1.y+b1v.y; c1.z += a1.z+b1v.z; c1.w += a1.w+b1v.w;
        }
        for (; j < hi; j++){
            int a = __ldg(cs+j);
            const float4* ra = (const float4*)(hW + (size_t)a*D2);
            float4 a0=__ldg(ra+lane), a1=__ldg(ra+lane+32);
            c0.x+=a0.x; c0.y+=a0.y; c0.z+=a0.z; c0.w+=a0.w;
            c1.x+=a1.x; c1.y+=a1.y; c1.z+=a1.z; c1.w+=a1.w;
        }
        c0.x+=bb0.x; c0.y+=bb0.y; c0.z+=bb0.z; c0.w+=bb0.w;
        c1.x+=bb1.x; c1.y+=bb1.y; c1.z+=bb1.z; c1.w+=bb1.w;

        float4* out = (float4*)(Y1 + (size_t)k*NPAD*D2 + (size_t)gw*D2);
        out[lane] = c0;
        out[lane+32] = c1;

        s0.x+=c0.x; s0.y+=c0.y; s0.z+=c0.z; s0.w+=c0.w;
        q0.x+=c0.x*c0.x; q0.y+=c0.y*c0.y; q0.z+=c0.z*c0.z; q0.w+=c0.w*c0.w;
        s1.x+=c1.x; s1.y+=c1.y; s1.z+=c1.z; s1.w+=c1.w;
        q1.x+=c1.x*c1.x; q1.y+=c1.y*c1.y; q1.z+=c1.z*c1.z; q1.w+=c1.w*c1.w;
    }

    int c0i = lane*4, c1i = 128 + lane*4;
    atomicAdd(&ssum[c0i+0], s0.x); atomicAdd(&ssum[c0i+1], s0.y);
    atomicAdd(&ssum[c0i+2], s0.z); atomicAdd(&ssum[c0i+3], s0.w);
    atomicAdd(&ssq [c0i+0], q0.x); atomicAdd(&ssq [c0i+1], q0.y);
    atomicAdd(&ssq [c0i+2], q0.z); atomicAdd(&ssq [c0i+3], q0.w);
    atomicAdd(&ssum[c1i+0], s1.x); atomicAdd(&ssum[c1i+1], s1.y);
    atomicAdd(&ssum[c1i+2], s1.z); atomicAdd(&ssum[c1i+3], s1.w);
    atomicAdd(&ssq [c1i+0], q1.x); atomicAdd(&ssq [c1i+1], q1.y);
    atomicAdd(&ssq [c1i+2], q1.z); atomicAdd(&ssq [c1i+3], q1.w);
    __syncthreads();
    if (tid < D2){
        atomicAdd(&gsum[k*D2 + tid], ssum[tid]);
        atomicAdd(&gsq [k*D2 + tid], ssq [tid]);
    }
}

// ---------------------------------------------------------------------------
// gemm1: pure-bf16 pipelined HMMA (unchanged)
// ---------------------------------------------------------------------------
template <int KTOT, int NTOT>
__global__ __launch_bounds__(256, 2) void bgemm_kernel(
    const __nv_bfloat16* __restrict__ Ahp, const __nv_bfloat16* __restrict__ Alp,
    const __nv_bfloat16* __restrict__ Bhp, const __nv_bfloat16* __restrict__ Blp,
    const float* __restrict__ bias,
    float* __restrict__ C, int M)
{
    extern __shared__ __align__(16) char dynsm[];
    __nv_bfloat16* sAh = (__nv_bfloat16*)(dynsm+OFF_AH);
    __nv_bfloat16* sAl = (__nv_bfloat16*)(dynsm+OFF_AL);
    __nv_bfloat16* sBh = (__nv_bfloat16*)(dynsm+OFF_BH);
    __nv_bfloat16* sBl = (__nv_bfloat16*)(dynsm+OFF_BL);

    const int tid=threadIdx.x, wid=tid>>5, lane=tid&31;
    const int wm=wid>>1, wn=wid&1;
    const int rowBase=blockIdx.x*BM, colBase=blockIdx.y*BN;
    const int ar=tid>>1, ahh=tid&1;
    const int br=tid>>4, bcv=tid&15;

    auto issue_tile=[&](int t,int s){
        const int kk=t*BK;
        __nv_bfloat16* ahDst=sAh+s*(128*40);
        __nv_bfloat16* alDst=sAl+s*(128*40);
#pragma unroll
        for (int j=0;j<2;j++){
            int col = ahh*16 + j*8;
            cp16(ahDst+ar*40+col, Ahp+(size_t)(rowBase+ar)*KTOT+kk+col);
            cp16(alDst+ar*40+col, Alp+(size_t)(rowBase+ar)*KTOT+kk+col);
        }
        __nv_bfloat16* bhDst=sBh+s*(32*136);
        __nv_bfloat16* blDst=sBl+s*(32*136);
#pragma unroll
        for (int p=0;p<2;p++){
            int r=br+p*16;
            cp16(bhDst+r*136+bcv*8, Bhp+(size_t)(kk+r)*NTOT+colBase+bcv*8);
            cp16(blDst+r*136+bcv*8, Blp+(size_t)(kk+r)*NTOT+colBase+bcv*8);
        }
    };

    issue_tile(0,0);
    asm volatile("cp.async.commit_group;":::"memory");

    float acc[2][8][4];
#pragma unroll
    for (int m=0;m<2;m++)
#pragma unroll
        for (int n=0;n<8;n++)
#pragma unroll
            for (int q=0;q<4;q++) acc[m][n][q]=0.f;

    const int ktiles=KTOT/BK;
    for (int t=0;t<ktiles;t++){
        const int s=t&1;
        asm volatile("cp.async.wait_group 0;":::"memory");
        __syncthreads();
        if (t+1<ktiles){ issue_tile(t+1,s^1); asm volatile("cp.async.commit_group;":::"memory"); }

        const __nv_bfloat16 *ah_s=sAh+s*(128*40), *al_s=sAl+s*(128*40);
        const __nv_bfloat16 *bh_s=sBh+s*(32*136), *bl_s=sBl+s*(32*136);
#pragma unroll
        for (int kb=0;kb<BK/16;kb++){
            uint32_t ah[2][4], al[2][4], bf[8][2];
#pragma unroll
            for (int m=0;m<2;m++){
                int row=wm*32+m*16+(lane&15), col=kb*16+(lane>>4)*8;
                ldsm_x4(ah[m], smem_u32(ah_s+row*40+col));
                ldsm_x4(al[m], smem_u32(al_s+row*40+col));
            }
#pragma unroll
            for (int nb=0;nb<4;nb++){
                int row=kb*16+(lane&15), col=wn*64+nb*16+(lane>>4)*8;
                uint32_t tr[4];
                ldsm_x4t(tr, smem_u32(bh_s+row*136+col));
                bf[nb*2][0]=tr[0]; bf[nb*2][1]=tr[1];
                bf[nb*2+1][0]=tr[2]; bf[nb*2+1][1]=tr[3];
            }
#pragma unroll
            for (int m=0;m<2;m++)
#pragma unroll
                for (int n=0;n<8;n++) mma16816(acc[m][n],ah[m],bf[n]);
#pragma unroll
            for (int m=0;m<2;m++)
#pragma unroll
                for (int n=0;n<8;n++) mma16816(acc[m][n],al[m],bf[n]);
#pragma unroll
            for (int nb=0;nb<4;nb++){
                int row=kb*16+(lane&15), col=wn*64+nb*16+(lane>>4)*8;
                uint32_t tr[4];
                ldsm_x4t(tr, smem_u32(bl_s+row*136+col));
                bf[nb*2][0]=tr[0]; bf[nb*2][1]=tr[1];
                bf[nb*2+1][0]=tr[2]; bf[nb*2+1][1]=tr[3];
            }
#pragma unroll
            for (int m=0;m<2;m++)
#pragma unroll
                for (int n=0;n<8;n++) mma16816(acc[m][n],ah[m],bf[n]);
        }
    }

#pragma unroll
    for (int m=0;m<2;m++){
        int rbase=rowBase+wm*32+m*16+(lane>>2);
#pragma unroll
        for (int half=0;half<2;half++){
            int rr=rbase+half*8;
            if (rr<M){
#pragma unroll
                for (int n=0;n<8;n++){
                    int c=colBase+wn*64+n*8+(lane&3)*2;
                    float2 o;
                    o.x=acc[m][n][half*2+0]+bias[c];
                    o.y=acc[m][n][half*2+1]+bias[c+1];
                    *(float2*)(C+(size_t)rr*NTOT+c)=o;
                }
            }
        }
    }
}

// ---------------------------------------------------------------------------
// gemm2 FUSED with combine: A = sum_k aw[k]*relu(y1_k*sc_k+sh_k), computed in
// the convert stage from 3 cp.async'd fp32 y1 tiles. C = A @ W2 + b2.
// ---------------------------------------------------------------------------
__global__ __launch_bounds__(256, 1) void fgemm2_kernel(
    const float* __restrict__ Y1,
    const __nv_bfloat16* __restrict__ Bhp, const __nv_bfloat16* __restrict__ Blp,
    const float* __restrict__ bias,
    const float* __restrict__ scale, const float* __restrict__ shift,
    const float* __restrict__ aw,
    float* __restrict__ C, int M)
{
    constexpr int KTOT = D2, NTOT = D;
    extern __shared__ __align__(16) char dynsm[];
    float*         sRaw = (float*)        (dynsm+F_RAW);   // [2][3][128][32]
    __nv_bfloat16* sAh  = (__nv_bfloat16*)(dynsm+F_AH);    // [2][128][40]
    __nv_bfloat16* sAl  = (__nv_bfloat16*)(dynsm+F_AL);
    __nv_bfloat16* sBh  = (__nv_bfloat16*)(dynsm+F_BH);    // [2][32][136]
    __nv_bfloat16* sBl  = (__nv_bfloat16*)(dynsm+F_BL);
    float*         sSc  = (float*)        (dynsm+F_SC);    // [3][256]
    float*         sSh  = (float*)        (dynsm+F_SH);

    const int tid=threadIdx.x, wid=tid>>5, lane=tid&31;
    const int wm=wid>>1, wn=wid&1;
    const int rowBase=blockIdx.x*BM;

    for (int i=tid; i<KS*D2; i+=256){ sSc[i]=scale[i]; sSh[i]=shift[i]; }
    const float aw0=__ldg(aw), aw1=__ldg(aw+1), aw2=__ldg(aw+2);

    const int ar=tid>>3, acv=tid&7;    // A: 32 rows/pass, float4 col
    const int br=tid>>4, bcv=tid&15;

    auto issue_tile=[&](int t,int s){
        const int kk=t*BK;
#pragma unroll
        for (int k=0;k<KS;k++){
            float* dst = sRaw + (s*KS+k)*(128*32);
            const float* src = Y1 + (size_t)k*NPAD*KTOT;
#pragma unroll
            for (int p=0;p<4;p++){
                int r=ar+p*32;
                cp16(dst+r*32+acv*4, src+(size_t)(rowBase+r)*KTOT+kk+acv*4);
            }
        }
        __nv_bfloat16* bhDst=sBh+s*(32*136);
        __nv_bfloat16* blDst=sBl+s*(32*136);
#pragma unroll
        for (int p=0;p<2;p++){
            int r=br+p*16;
            cp16(bhDst+r*136+bcv*8, Bhp+(size_t)(kk+r)*NTOT+bcv*8);
            cp16(blDst+r*136+bcv*8, Blp+(size_t)(kk+r)*NTOT+bcv*8);
        }
    };

    issue_tile(0,0);
    asm volatile("cp.async.commit_group;":::"memory");

    float acc[2][8][4];
#pragma unroll
    for (int m=0;m<2;m++)
#pragma unroll
        for (int n=0;n<8;n++)
#pragma unroll
            for (int q=0;q<4;q++) acc[m][n][q]=0.f;

    const int ktiles=KTOT/BK;
    for (int t=0;t<ktiles;t++){
        const int s=t&1;
        asm volatile("cp.async.wait_group 0;":::"memory");
        __syncthreads();   // raw[t] + (t==0: sSc/sSh) visible
        if (t+1<ktiles){ issue_tile(t+1,s^1); asm volatile("cp.async.commit_group;":::"memory"); }

        // convert: zc = sum_k aw_k * relu(y1_k*sc_k+sh_k), split to planes
        {
            const int kk=t*BK;
            __nv_bfloat16* hDst=sAh+s*(128*40);
            __nv_bfloat16* lDst=sAl+s*(128*40);
#pragma unroll
            for (int p=0;p<4;p++){
                int r=ar+p*32;
                float4 accv = make_float4(0.f,0.f,0.f,0.f);
#pragma unroll
                for (int k=0;k<KS;k++){
                    const float* rawk = sRaw + (s*KS+k)*(128*32);
                    float4 v = *(const float4*)(rawk + r*32 + acv*4);
                    int c = k*D2 + kk + acv*4;
                    float a = (k==0)?aw0:((k==1)?aw1:aw2);
                    accv.x += a*fmaxf(fmaf(v.x, sSc[c+0], sSh[c+0]), 0.f);
                    accv.y += a*fmaxf(fmaf(v.y, sSc[c+1], sSh[c+1]), 0.f);
                    accv.z += a*fmaxf(fmaf(v.z, sSc[c+2], sSh[c+2]), 0.f);
                    accv.w += a*fmaxf(fmaf(v.w, sSc[c+3], sSh[c+3]), 0.f);
                }
                uint2 hp, lp;
                split4(accv, hp, lp);
                *(uint2*)(hDst + r*40 + acv*4) = hp;
                *(uint2*)(lDst + r*40 + acv*4) = lp;
            }
        }
        __syncthreads();

        const __nv_bfloat16 *ah_s=sAh+s*(128*40), *al_s=sAl+s*(128*40);
        const __nv_bfloat16 *bh_s=sBh+s*(32*136), *bl_s=sBl+s*(32*136);
#pragma unroll
        for (int kb=0;kb<BK/16;kb++){
            uint32_t ah[2][4], al[2][4], bf[8][2];
#pragma unroll
            for (int m=0;m<2;m++){
                int row=wm*32+m*16+(lane&15), col=kb*16+(lane>>4)*8;
                ldsm_x4(ah[m], smem_u32(ah_s+row*40+col));
                ldsm_x4(al[m], smem_u32(al_s+row*40+col));
            }
#pragma unroll
            for (int nb=0;nb<4;nb++){
                int row=kb*16+(lane&15), col=wn*64+nb*16+(lane>>4)*8;
                uint32_t tr[4];
                ldsm_x4t(tr, smem_u32(bh_s+row*136+col));
                bf[nb*2][0]=tr[0]; bf[nb*2][1]=tr[1];
                bf[nb*2+1][0]=tr[2]; bf[nb*2+1][1]=tr[3];
            }
#pragma unroll
            for (int m=0;m<2;m++)
#pragma unroll
                for (int n=0;n<8;n++) mma16816(acc[m][n],ah[m],bf[n]);
#pragma unroll
            for (int m=0;m<2;m++)
#pragma unroll
                for (int n=0;n<8;n++) mma16816(acc[m][n],al[m],bf[n]);
#pragma unroll
            for (int nb=0;nb<4;nb++){
                int row=kb*16+(lane&15), col=wn*64+nb*16+(lane>>4)*8;
                uint32_t tr[4];
                ldsm_x4t(tr, smem_u32(bl_s+row*136+col));
                bf[nb*2][0]=tr[0]; bf[nb*2][1]=tr[1];
                bf[nb*2+1][0]=tr[2]; bf[nb*2+1][1]=tr[3];
            }
#pragma unroll
            for (int m=0;m<2;m++)
#pragma unroll
                for (int n=0;n<8;n++) mma16816(acc[m][n],ah[m],bf[n]);
        }
    }

#pragma unroll
    for (int m=0;m<2;m++){
        int rbase=rowBase+wm*32+m*16+(lane>>2);
#pragma unroll
        for (int half=0;half<2;half++){
            int rr=rbase+half*8;
            if (rr<M){
#pragma unroll
                for (int n=0;n<8;n++){
                    int c=wn*64+n*8+(lane&3)*2;
                    float2 o;
                    o.x=acc[m][n][half*2+0]+bias[c];
                    o.y=acc[m][n][half*2+1]+bias[c+1];
                    *(float2*)(C+(size_t)rr*NTOT+c)=o;
                }
            }
        }
    }
}

__global__ void colstats_kernel(const float* __restrict__ X, int M, int C,
                                float* __restrict__ s, float* __restrict__ q)
{
    int c = threadIdx.x;
    float ps=0.f, pq=0.f;
    for (int r=blockIdx.x; r<M; r+=gridDim.x){
        float v = X[(size_t)r*C+c];
        ps += v; pq += v*v;
    }
    atomicAdd(&s[c],ps); atomicAdd(&q[c],pq);
}

__global__ void finalize_kernel(const float* __restrict__ s, const float* __restrict__ q,
                                const float* __restrict__ g, const float* __restrict__ b,
                                float* __restrict__ scale, float* __restrict__ shift,
                                float invN, int C)
{
    int k = blockIdx.x, c = threadIdx.x;
    float mu = s[k*C+c]*invN;
    float var = q[k*C+c]*invN - mu*mu;
    float rstd = rsqrtf(var+1e-5f);
    float sc = rstd*g[c];
    scale[k*C+c] = sc;
    shift[k*C+c] = b[c]-mu*sc;
}

__global__ void bnrelu_kernel(const float* __restrict__ X, const float* __restrict__ scale,
                              const float* __restrict__ shift, float* __restrict__ Out, int n4)
{
    int i = blockIdx.x*blockDim.x+threadIdx.x;
    if (i >= n4) return;
    int c4 = i & 31;
    float4 v  = ((const float4*)X)[i];
    float4 sc = ((const float4*)scale)[c4];
    float4 sh = ((const float4*)shift)[c4];
    v.x=fmaxf(fmaf(v.x,sc.x,sh.x),0.f);
    v.y=fmaxf(fmaf(v.y,sc.y,sh.y),0.f);
    v.z=fmaxf(fmaf(v.z,sc.z,sh.z),0.f);
    v.w=fmaxf(fmaf(v.w,sc.w,sh.w),0.f);
    ((float4*)Out)[i] = v;
}

// ---------------------------------------------------------------------------
extern "C" void kernel_launch(void* const* d_in, const int* in_sizes, int n_in,
                              void* d_out, int out_size)
{
    const int*   x     = (const int*)  d_in[0];
    const int*   ke    = (const int*)  d_in[1];
    const float* emb   = (const float*)d_in[2];
    const float* W1    = (const float*)d_in[3];
    const float* b1    = (const float*)d_in[4];
    const float* g1    = (const float*)d_in[5];
    const float* be1   = (const float*)d_in[6];
    const float* W2    = (const float*)d_in[7];
    const float* b2    = (const float*)d_in[8];
    const float* eps   = (const float*)d_in[9];
    const float* alpha = (const float*)d_in[10];
    const float* bn_g  = (const float*)d_in[11];
    const float* bn_b  = (const float*)d_in[12];

    const int N = in_sizes[0]/NFEAT;
    const int E = in_sizes[1]/(KS*2);
    const int n4  = N*(D/4);
    const int nTilesM = (N+BM-1)/BM;

    float *p_hW,*p_y1,*p_hacc,*p_sum,*p_sq,*p_scale,*p_shift,*p_scaleD,*p_shiftD,*p_aw,*p_zero;
    __nv_bfloat16 *p_hH,*p_hL,*p_w1h,*p_w1l,*p_w2h,*p_w2l;
    int *p_deg,*p_dcur,*p_rowptr,*p_csrc;
    cudaGetSymbolAddress((void**)&p_hW,g_hW);
    cudaGetSymbolAddress((void**)&p_y1,g_y1);
    cudaGetSymbolAddress((void**)&p_hacc,g_hacc);
    cudaGetSymbolAddress((void**)&p_hH,g_hH);
    cudaGetSymbolAddress((void**)&p_hL,g_hL);
    cudaGetSymbolAddress((void**)&p_sum,g_sum);
    cudaGetSymbolAddress((void**)&p_sq,g_sq);
    cudaGetSymbolAddress((void**)&p_scale,g_scale);
    cudaGetSymbolAddress((void**)&p_shift,g_shift);
    cudaGetSymbolAddress((void**)&p_scaleD,g_scaleD);
    cudaGetSymbolAddress((void**)&p_shiftD,g_shiftD);
    cudaGetSymbolAddress((void**)&p_aw,g_aw);
    cudaGetSymbolAddress((void**)&p_zero,g_zero);
    cudaGetSymbolAddress((void**)&p_w1h,g_W1h);
    cudaGetSymbolAddress((void**)&p_w1l,g_W1l);
    cudaGetSymbolAddress((void**)&p_w2h,g_W2h);
    cudaGetSymbolAddress((void**)&p_w2l,g_W2l);
    cudaGetSymbolAddress((void**)&p_deg,g_deg);
    cudaGetSymbolAddress((void**)&p_dcur,g_dcur);
    cudaGetSymbolAddress((void**)&p_rowptr,g_rowptr);
    cudaGetSymbolAddress((void**)&p_csrc,g_csrc);

    cudaFuncSetAttribute(bgemm_kernel<D, D2>,
                         cudaFuncAttributeMaxDynamicSharedMemorySize, SMEM_BYTES);
    cudaFuncSetAttribute(fgemm2_kernel,
                         cudaFuncAttributeMaxDynamicSharedMemorySize, F_SMEM);

    const float invN = 1.0f/(float)N;

    {
        int tot = 2*LAY*D*D2;
        wsplit_kernel<<<(tot+255)/256, 256>>>(W1, W2, p_w1h, p_w1l, p_w2h, p_w2l);
    }
    cudaMemsetAsync(p_deg, 0, (size_t)KS*N*sizeof(int));
    hist_kernel<<<(KS*E+255)/256, 256>>>(ke, p_deg, E, N);
    scan_kernel<<<KS, 1024>>>(p_deg, p_rowptr, p_dcur, N, E);
    fill_kernel<<<(KS*E+255)/256, 256>>>(ke, p_dcur, p_csrc, E, N);

    embed_split_kernel<<<(N*32+255)/256, 256>>>(x, emb, p_hH, p_hL, N);

    for (int l = 0; l < LAY; l++){
        softmax3_kernel<<<1,1>>>(alpha+l*KS, p_aw);

        if (l > 0)
            bnrelu_split_kernel<<<(n4+255)/256, 256>>>(p_hacc, p_scaleD, p_shiftD, p_hH, p_hL, n4);

        // hW = h @ W1
        bgemm_kernel<D, D2><<<dim3(nTilesM, 2), 256, SMEM_BYTES>>>(
            p_hH, p_hL, p_w1h+(size_t)l*D*D2, p_w1l+(size_t)l*D*D2, p_zero, p_hW, N);

        // y1_k = (1+eps)hW + gather + b1, fused stats
        cudaMemsetAsync(p_sum, 0, KS*D2*sizeof(float));
        cudaMemsetAsync(p_sq,  0, KS*D2*sizeof(float));
        aggregate256_stats_kernel<<<dim3((N+63)/64, KS), 256>>>(
            p_hW, p_rowptr, p_csrc, eps+l, b1+l*D2, p_y1, p_sum, p_sq, N, E);
        finalize_kernel<<<KS, D2>>>(p_sum, p_sq, g1+l*D2, be1+l*D2, p_scale, p_shift, invN, D2);

        // hacc = [sum_k aw_k relu(BN_k(y1_k))] @ W2 + b2  (combine fused in)
        fgemm2_kernel<<<dim3(nTilesM, 1), 256, F_SMEM>>>(
            p_y1, p_w2h+(size_t)l*D2*D, p_w2l+(size_t)l*D2*D, b2+l*D,
            p_scale, p_shift, p_aw, p_hacc, N);

        cudaMemsetAsync(p_sum, 0, D*sizeof(float));
        cudaMemsetAsync(p_sq,  0, D*sizeof(float));
        colstats_kernel<<<2048, D>>>(p_hacc, N, D, p_sum, p_sq);
        finalize_kernel<<<1, D>>>(p_sum, p_sq, bn_g+l*D, bn_b+l*D, p_scaleD, p_shiftD, invN, D);

        if (l == LAY-1)
            bnrelu_kernel<<<(n4+255)/256, 256>>>(p_hacc, p_scaleD, p_shiftD, (float*)d_out, n4);
    }
}